// round 3
// baseline (speedup 1.0000x reference)
#include <cuda_runtime.h>
#include <cstdint>
#include <cstdio>

#define B_ 64
#define T_ 512
#define EMB_ 128
#define HID_ 256
#define MEL_ 80
#define LMAX_ 2048

typedef unsigned long long ull;

// ---------------- static device scratch (no allocations allowed) ----------------
__device__ int   g_durTab[256];
__device__ int   g_tok[B_ * LMAX_];                 // vocab id per expanded pos, 256 = pad
__device__ float g_projE[2 * 257 * 1024];           // Wih@embed[v] + bih + bhh  (entry 256 = bias only)
__device__ float g_hout[2ull * B_ * LMAX_ * HID_];  // [dir][b][pos][256] (pos stride uses runtime L)

// ---------------- helpers ----------------
__device__ __forceinline__ ull fma2(ull a, ull b, ull c) {   // packed: d = a*b + c (2x f32)
    ull d;
    asm("fma.rn.f32x2 %0, %1, %2, %3;" : "=l"(d) : "l"(a), "l"(b), "l"(c));
    return d;
}
__device__ __forceinline__ float pairsum(ull v) {
    float x, y;
    asm("mov.b64 {%0, %1}, %2;" : "=f"(x), "=f"(y) : "l"(v));
    return x + y;
}
__device__ __forceinline__ float sigf(float x)  { return __fdividef(1.f, 1.f + __expf(-x)); }
__device__ __forceinline__ float tanhf_(float x){ return 1.f - __fdividef(2.f, 1.f + __expf(2.f * x)); }

// ---------------- K1a: per-vocab duration table ----------------
__global__ void k_durtab(const float* __restrict__ embed, const float* __restrict__ dpw,
                         const float* __restrict__ dpb) {
    __shared__ float w[EMB_];
    int t = threadIdx.x;           // 0..255 = vocab id
    if (t < EMB_) w[t] = dpw[t];
    __syncthreads();
    const float* e = embed + t * EMB_;
    double acc = (double)dpb[0];
#pragma unroll 8
    for (int k = 0; k < EMB_; k++) acc += (double)e[k] * (double)w[k];
    float d = (float)acc;
    if (d < 0.f) d = 0.f;
    g_durTab[t] = (int)floorf(d) + 1;
}

// ---------------- K1b: per-batch scan + token scatter ----------------
__global__ void k_expand(const int* __restrict__ x) {
    __shared__ int s[T_];
    int b = blockIdx.x, t = threadIdx.x;
    int tokid = x[b * T_ + t];
    s[t] = g_durTab[tokid];
    __syncthreads();
    for (int off = 1; off < T_; off <<= 1) {
        int v = s[t];
        int a = (t >= off) ? s[t - off] : 0;
        __syncthreads();
        s[t] = v + a;
        __syncthreads();
    }
    for (int p = t; p < LMAX_; p += T_) g_tok[b * LMAX_ + p] = 256;   // pad
    __syncthreads();
    int st = t ? s[t - 1] : 0;
    int en = s[t];
    if (en > LMAX_) en = LMAX_;
    for (int p = st; p < en; p++) g_tok[b * LMAX_ + p] = tokid;
}

// ---------------- K2: per-vocab input-projection tables ----------------
__global__ void k_proj(const float* __restrict__ embed,
                       const float* __restrict__ wih_f, const float* __restrict__ bih_f,
                       const float* __restrict__ bhh_f,
                       const float* __restrict__ wih_b, const float* __restrict__ bih_b,
                       const float* __restrict__ bhh_b) {
    __shared__ float e[EMB_];
    int v = blockIdx.x;            // 0..256 (256 = bias-only/pad entry)
    int dir = blockIdx.y;
    const float* wih = dir ? wih_b : wih_f;
    const float* bi  = dir ? bih_b : bih_f;
    const float* bh  = dir ? bhh_b : bhh_f;
    int t = threadIdx.x;
    if (t < EMB_) e[t] = (v < 256) ? embed[v * EMB_ + t] : 0.f;
    __syncthreads();
#pragma unroll
    for (int i = 0; i < 4; i++) {
        int r = t + 256 * i;
        float acc = 0.f;
#pragma unroll 8
        for (int k = 0; k < EMB_; k++) acc += wih[r * EMB_ + k] * e[k];
        g_projE[(dir * 257 + v) * 1024 + r] = acc + bi[r] + bh[r];
    }
}

// ---------------- K3: persistent cluster biLSTM ----------------
// 16 clusters x 8 CTAs. cluster = (dir, batch-group of 8). CTA rank = 32-wide hidden slice.
// Whh slice (128 rows x 256) lives in registers: 128 floats/thread packed as 64 u64.
__global__ void __cluster_dims__(8, 1, 1) __launch_bounds__(256, 1)
k_lstm(const float* __restrict__ whh_f, const float* __restrict__ whh_b, int L) {
    __shared__ __align__(16) float hbuf[2][8][256];   // double-buffered h for 8 batch rows
    __shared__ float scr[8 * 256];                    // stage-1 partials [b][kh*128 + gate*32 + j]

    int tid = threadIdx.x;
    int w = tid >> 5, l = tid & 31;
    int bx = blockIdx.x;
    int rank = bx & 7;            // hidden slice
    int cid = bx >> 3;
    int dir = cid >> 3;           // 0 = fwd, 1 = bwd
    int bbase = (cid & 7) * 8;
    const float* whh = dir ? whh_b : whh_f;

    // stage-1 identity: kh = K-half, rg = gate (0..3), row-in-gate = l
    int kh = w & 1, rg = w >> 1;
    // preload weight half-row into registers (step-invariant)
    const ulonglong2* wp =
        (const ulonglong2*)(whh + ((rg * 256 + rank * 32 + l) * 256 + kh * 128));
    ull wr[64];
#pragma unroll
    for (int i = 0; i < 32; i++) { ulonglong2 u = wp[i]; wr[2 * i] = u.x; wr[2 * i + 1] = u.y; }

    // zero both h buffers
    for (int i = tid; i < 2 * 8 * 256; i += 256) ((float*)hbuf)[i] = 0.f;

    // stage-2 identity: batch b2 = w, hidden j2 = l
    int b2 = w, j2 = l;
    int bg = bbase + b2;
    float c = 0.f;
    uint32_t hb_s = (uint32_t)__cvta_generic_to_shared(hbuf);
    uint32_t myoff = (uint32_t)((b2 * 256 + rank * 32 + j2) * 4);

    int p = 0;
    asm volatile("barrier.cluster.arrive.aligned;\n\tbarrier.cluster.wait.aligned;" ::: "memory");

    for (int s = 0; s < L; s++) {
        int pos = dir ? (L - 1 - s) : s;
        // early gathers for stage 2 (consumed ~2000 cyc later)
        int tok = g_tok[bg * LMAX_ + pos];
        const float* pe = g_projE + (dir * 257 + tok) * 1024 + rank * 32 + j2;
        float p_i = pe[0], p_f = pe[256], p_g = pe[512], p_o = pe[768];

        // ---- stage 1: 128-long half-dot for my gate row, for 8 batch rows ----
        const float* hb = &hbuf[p][0][kh * 128];
        ull acc[8];
#pragma unroll
        for (int b = 0; b < 8; b++) acc[b] = 0ull;
#pragma unroll
        for (int kq = 0; kq < 32; kq++) {
#pragma unroll
            for (int b = 0; b < 8; b++) {
                ulonglong2 hv = *(const ulonglong2*)(hb + b * 256 + kq * 4);
                acc[b] = fma2(wr[2 * kq], hv.x, acc[b]);
                acc[b] = fma2(wr[2 * kq + 1], hv.y, acc[b]);
            }
        }
        int sbase = kh * 128 + rg * 32 + l;
#pragma unroll
        for (int b = 0; b < 8; b++) scr[b * 256 + sbase] = pairsum(acc[b]);
        __syncthreads();

        // ---- stage 2: combine halves + gates, update c/h for (b2, j2) ----
        const float* sb = scr + b2 * 256;
        float gi = p_i + sb[      j2] + sb[128 +      j2];
        float gf = p_f + sb[ 32 + j2] + sb[128 + 32 + j2];
        float gg = p_g + sb[ 64 + j2] + sb[128 + 64 + j2];
        float go = p_o + sb[ 96 + j2] + sb[128 + 96 + j2];
        c = sigf(gf) * c + sigf(gi) * tanhf_(gg);
        float h = sigf(go) * tanhf_(c);

        g_hout[(((size_t)dir * 64 + bg) * L + pos) * 256 + rank * 32 + j2] = h;

        // broadcast my h element into every cluster CTA's next buffer
        uint32_t dst = hb_s + (uint32_t)((p ^ 1) * 8 * 256 * 4) + myoff;
#pragma unroll
        for (int r = 0; r < 8; r++) {
            uint32_t ra;
            asm volatile("mapa.shared::cluster.u32 %0, %1, %2;" : "=r"(ra) : "r"(dst), "r"(r));
            asm volatile("st.shared::cluster.f32 [%0], %1;" :: "r"(ra), "f"(h) : "memory");
        }
        asm volatile("barrier.cluster.arrive.aligned;\n\tbarrier.cluster.wait.aligned;" ::: "memory");
        p ^= 1;
    }
}

// ---------------- K4: final linear (B*L, 512) @ (512, 80) + bias ----------------
#define SW 514
#define ROWS_LIN 24
__global__ void __launch_bounds__(192, 1)
k_lin(const float* __restrict__ linw, const float* __restrict__ linb,
      float* __restrict__ out, int L, int R) {
    extern __shared__ float sm[];
    float* sw = sm;               // [80][SW]
    float* sh = sm + 80 * SW;     // [ROWS_LIN][SW]
    int tid = threadIdx.x;
    int r0g = blockIdx.x * ROWS_LIN;

    // load weights (m-major, padded stride for conflict-free u64 reads)
    for (int i = tid; i < 80 * 256; i += 192) {
        int m = i >> 8, k = (i & 255) * 2;
        float2 v = *(const float2*)(linw + m * 512 + k);
        *(float2*)(sw + m * SW + k) = v;
    }
    // load h tile (concat fwd|bwd)
    for (int i = tid; i < ROWS_LIN * 128; i += 192) {
        int rl = i >> 7, k = (i & 127) * 4;
        int rg = r0g + rl;
        float4 v = make_float4(0.f, 0.f, 0.f, 0.f);
        if (rg < R) {
            int b = rg / L, pos = rg % L;
            int d = k >> 8, j = k & 255;
            v = *(const float4*)(g_hout + (((size_t)d * 64 + b) * L + pos) * 256 + j);
        }
        *(float2*)(sh + rl * SW + k)     = make_float2(v.x, v.y);
        *(float2*)(sh + rl * SW + k + 2) = make_float2(v.z, v.w);
    }
    __syncthreads();

    int mg = tid & 15, rp = tid >> 4;   // 16 m-groups x 12 row-pairs
    int ra = rp * 2, rb = rp * 2 + 1;
    ull a0[5], a1[5];
#pragma unroll
    for (int i = 0; i < 5; i++) { a0[i] = 0ull; a1[i] = 0ull; }
#pragma unroll 8
    for (int kp = 0; kp < 256; kp++) {
        int k = kp * 2;
        ull h0 = *(const ull*)(sh + ra * SW + k);
        ull h1 = *(const ull*)(sh + rb * SW + k);
#pragma unroll
        for (int i = 0; i < 5; i++) {
            ull wv = *(const ull*)(sw + (mg + 16 * i) * SW + k);
            a0[i] = fma2(wv, h0, a0[i]);
            a1[i] = fma2(wv, h1, a1[i]);
        }
    }
#pragma unroll
    for (int i = 0; i < 5; i++) {
        int m = mg + 16 * i;
        float bm = linb[m];
        int rga = r0g + ra, rgb = r0g + rb;
        if (rga < R) out[(size_t)rga * MEL_ + m] = pairsum(a0[i]) + bm;
        if (rgb < R) out[(size_t)rgb * MEL_ + m] = pairsum(a1[i]) + bm;
    }
}

// ---------------- launch ----------------
extern "C" void kernel_launch(void* const* d_in, const int* in_sizes, int n_in,
                              void* d_out, int out_size) {
    const int*   x     = (const int*)  d_in[0];
    const float* embed = (const float*)d_in[1];
    const float* dpw   = (const float*)d_in[2];
    const float* dpb   = (const float*)d_in[3];
    const float* wihf  = (const float*)d_in[4];
    const float* whhf  = (const float*)d_in[5];
    const float* bihf  = (const float*)d_in[6];
    const float* bhhf  = (const float*)d_in[7];
    const float* wihb  = (const float*)d_in[8];
    const float* whhb  = (const float*)d_in[9];
    const float* bihb  = (const float*)d_in[10];
    const float* bhhb  = (const float*)d_in[11];
    const float* linw  = (const float*)d_in[12];
    const float* linb  = (const float*)d_in[13];
    float* out = (float*)d_out;

    int L = out_size / (B_ * MEL_);
    if (L > LMAX_) L = LMAX_;
    int R = B_ * L;

    k_durtab<<<1, 256>>>(embed, dpw, dpb);
    k_expand<<<B_, T_>>>(x);
    k_proj<<<dim3(257, 2, 1), 256>>>(embed, wihf, bihf, bhhf, wihb, bihb, bhhb);
    k_lstm<<<128, 256>>>(whhf, whhb, L);

    int smem = 104 * SW * 4;   // 213,824 B
    cudaFuncSetAttribute(k_lin, cudaFuncAttributeMaxDynamicSharedMemorySize, smem);
    k_lin<<<(R + ROWS_LIN - 1) / ROWS_LIN, 192, smem>>>(linw, linb, out, L, R);
}

// round 4
// speedup vs baseline: 1.1167x; 1.1167x over previous
#include <cuda_runtime.h>
#include <cstdint>
#include <cstdio>

#define B_ 64
#define T_ 512
#define EMB_ 128
#define HID_ 256
#define MEL_ 80
#define LMAX_ 2048

typedef unsigned long long ull;

// ---------------- static device scratch (no allocations allowed) ----------------
__device__ int   g_durTab[256];
__device__ int   g_tok[B_ * LMAX_];                 // vocab id per expanded pos, 256 = pad
__device__ float g_projE[2 * 257 * 1024];           // Wih@embed[v] + bih + bhh  (entry 256 = bias only)
__device__ float g_hout[2ull * B_ * LMAX_ * HID_];  // [dir][b][pos][256]

// ---------------- helpers ----------------
__device__ __forceinline__ ull fma2(ull a, ull b, ull c) {   // packed: d = a*b + c (2x f32)
    ull d;
    asm("fma.rn.f32x2 %0, %1, %2, %3;" : "=l"(d) : "l"(a), "l"(b), "l"(c));
    return d;
}
__device__ __forceinline__ float pairsum(ull v) {
    float x, y;
    asm("mov.b64 {%0, %1}, %2;" : "=f"(x), "=f"(y) : "l"(v));
    return x + y;
}
__device__ __forceinline__ float sigf(float x)  { return __fdividef(1.f, 1.f + __expf(-x)); }
__device__ __forceinline__ float tanhf_(float x){ return 1.f - __fdividef(2.f, 1.f + __expf(2.f * x)); }

__device__ __forceinline__ void cluster_sync() {
    asm volatile("barrier.cluster.arrive.aligned;" ::: "memory");
    asm volatile("barrier.cluster.wait.aligned;" ::: "memory");
}
__device__ __forceinline__ void mbar_init(uint32_t a, uint32_t cnt) {
    asm volatile("mbarrier.init.shared.b64 [%0], %1;" :: "r"(a), "r"(cnt) : "memory");
}
__device__ __forceinline__ void mbar_arrive_expect(uint32_t a, uint32_t tx) {
    asm volatile("mbarrier.arrive.expect_tx.shared.b64 _, [%0], %1;" :: "r"(a), "r"(tx) : "memory");
}
__device__ __forceinline__ void mbar_wait(uint32_t a, uint32_t par) {
    asm volatile(
        "{\n\t"
        ".reg .pred P;\n\t"
        "W%=:\n\t"
        "mbarrier.try_wait.parity.acquire.cluster.shared::cta.b64 P, [%0], %1;\n\t"
        "@P bra D%=;\n\t"
        "bra W%=;\n\t"
        "D%=:\n\t"
        "}"
        :: "r"(a), "r"(par) : "memory");
}
__device__ __forceinline__ void st_async_f32(uint32_t raddr, float v, uint32_t rmbar) {
    asm volatile("st.async.weak.shared::cluster.mbarrier::complete_tx::bytes.b32 [%0], %1, [%2];"
                 :: "r"(raddr), "f"(v), "r"(rmbar) : "memory");
}

// ---------------- K1a: per-vocab duration table ----------------
__global__ void k_durtab(const float* __restrict__ embed, const float* __restrict__ dpw,
                         const float* __restrict__ dpb) {
    __shared__ float w[EMB_];
    int t = threadIdx.x;           // 0..255 = vocab id
    if (t < EMB_) w[t] = dpw[t];
    __syncthreads();
    const float* e = embed + t * EMB_;
    double acc = (double)dpb[0];
#pragma unroll 8
    for (int k = 0; k < EMB_; k++) acc += (double)e[k] * (double)w[k];
    float d = (float)acc;
    if (d < 0.f) d = 0.f;
    g_durTab[t] = (int)floorf(d) + 1;
}

// ---------------- K1b: per-batch scan + token scatter ----------------
__global__ void k_expand(const int* __restrict__ x) {
    __shared__ int s[T_];
    int b = blockIdx.x, t = threadIdx.x;
    int tokid = x[b * T_ + t];
    s[t] = g_durTab[tokid];
    __syncthreads();
    for (int off = 1; off < T_; off <<= 1) {
        int v = s[t];
        int a = (t >= off) ? s[t - off] : 0;
        __syncthreads();
        s[t] = v + a;
        __syncthreads();
    }
    for (int p = t; p < LMAX_; p += T_) g_tok[b * LMAX_ + p] = 256;   // pad
    __syncthreads();
    int st = t ? s[t - 1] : 0;
    int en = s[t];
    if (en > LMAX_) en = LMAX_;
    for (int p = st; p < en; p++) g_tok[b * LMAX_ + p] = tokid;
}

// ---------------- K2: per-vocab input-projection tables ----------------
__global__ void k_proj(const float* __restrict__ embed,
                       const float* __restrict__ wih_f, const float* __restrict__ bih_f,
                       const float* __restrict__ bhh_f,
                       const float* __restrict__ wih_b, const float* __restrict__ bih_b,
                       const float* __restrict__ bhh_b) {
    __shared__ float e[EMB_];
    int v = blockIdx.x;            // 0..256 (256 = bias-only/pad entry)
    int dir = blockIdx.y;
    const float* wih = dir ? wih_b : wih_f;
    const float* bi  = dir ? bih_b : bih_f;
    const float* bh  = dir ? bhh_b : bhh_f;
    int t = threadIdx.x;
    if (t < EMB_) e[t] = (v < 256) ? embed[v * EMB_ + t] : 0.f;
    __syncthreads();
#pragma unroll
    for (int i = 0; i < 4; i++) {
        int r = t + 256 * i;
        float acc = 0.f;
#pragma unroll 8
        for (int k = 0; k < EMB_; k++) acc += wih[r * EMB_ + k] * e[k];
        g_projE[(dir * 257 + v) * 1024 + r] = acc + bi[r] + bh[r];
    }
}

// ---------------- K3: persistent cluster biLSTM ----------------
// 16 clusters x 8 CTAs x 512 threads. cluster = (dir, batch-group of 8).
// CTA rank owns 32-wide hidden slice (= 128 gate rows). Warp = (gate g, K-quarter kq),
// lane = hidden j. Per-thread weights: 64 floats in regs. h exchange: st.async + tx-mbarrier.
__global__ void __cluster_dims__(8, 1, 1) __launch_bounds__(512, 1)
k_lstm(const float* __restrict__ whh_f, const float* __restrict__ whh_b, int L) {
    __shared__ __align__(16) float hbuf[2][8][256];   // double-buffered h (8 seqs x 256)
    __shared__ float scr[8 * 512];                    // partials [b][kq*128 + g*32 + j]
    __shared__ __align__(8) ull mbars[2];

    int tid = threadIdx.x;
    int w = tid >> 5, l = tid & 31;
    int bx = blockIdx.x;
    int rank = bx & 7;            // hidden slice
    int cid = bx >> 3;
    int dir = cid >> 3;           // 0 = fwd, 1 = bwd
    int bbase = (cid & 7) * 8;
    const float* whh = dir ? whh_b : whh_f;

    // stage-1 identity: gate g = w>>2 (0..3), K-quarter kq = w&3, row j = l
    int g = w >> 2, kq = w & 3;
    const ulonglong2* wp =
        (const ulonglong2*)(whh + ((g * 256 + rank * 32 + l) * 256 + kq * 64));
    ull wr[32];                    // 64 floats of Whh, step-invariant
#pragma unroll
    for (int i = 0; i < 16; i++) { ulonglong2 u = wp[i]; wr[2 * i] = u.x; wr[2 * i + 1] = u.y; }

    for (int i = tid; i < 2 * 8 * 256; i += 512) ((float*)hbuf)[i] = 0.f;

    uint32_t hb_s = (uint32_t)__cvta_generic_to_shared(hbuf);
    uint32_t mb_s = (uint32_t)__cvta_generic_to_shared(mbars);
    if (tid == 0) {
        mbar_init(mb_s, 1);
        mbar_init(mb_s + 8, 1);
        asm volatile("fence.mbarrier_init.release.cluster;" ::: "memory");
        mbar_arrive_expect(mb_s, 8192);        // pre-arm both phases' first use
        mbar_arrive_expect(mb_s + 8, 8192);
    }
    __syncthreads();
    cluster_sync();                            // one-time: init+arm+zero visible cluster-wide

    // stage-2 identity: batch b2 = tid>>5, hidden j2 = tid&31 (first 256 threads)
    bool s2 = tid < 256;
    int b2 = tid >> 5, j2 = tid & 31;
    int bg = bbase + b2;
    float c = 0.f;
    uint32_t dstbase = hb_s + (uint32_t)((b2 * 256 + rank * 32 + j2) * 4);

    unsigned par0 = 0, par1 = 0;
    int p = 0;
    for (int s = 0; s < L; s++) {
        int pos = dir ? (L - 1 - s) : s;
        // early gathers for stage 2 (L1/L2 latency overlapped with wait + stage 1)
        float p_i = 0.f, p_f = 0.f, p_g = 0.f, p_o = 0.f;
        if (s2) {
            int tok = g_tok[bg * LMAX_ + pos];
            const float* pe = g_projE + (dir * 257 + tok) * 1024 + rank * 32 + j2;
            p_i = pe[0]; p_f = pe[256]; p_g = pe[512]; p_o = pe[768];
        }
        if (s > 0) {
            uint32_t mb = mb_s + (uint32_t)(p * 8);
            unsigned par = p ? par1 : par0;
            mbar_wait(mb, par);                // all 8 KB of h delivered for this phase
            if (p) par1 ^= 1; else par0 ^= 1;
            if (tid == 0) mbar_arrive_expect(mb, 8192);   // rearm 2 steps ahead (race-free)
        }

        // ---- stage 1: 64-long quarter-dot for my gate row, 8 batch rows ----
        const float* hb = &hbuf[p][0][kq * 64];
        ull acc[8];
#pragma unroll
        for (int b = 0; b < 8; b++) acc[b] = 0ull;
#pragma unroll
        for (int i = 0; i < 16; i++) {
#pragma unroll
            for (int b = 0; b < 8; b++) {
                ulonglong2 hv = *(const ulonglong2*)(hb + b * 256 + i * 4);
                acc[b] = fma2(wr[2 * i], hv.x, acc[b]);
                acc[b] = fma2(wr[2 * i + 1], hv.y, acc[b]);
            }
        }
        int sbase = kq * 128 + g * 32 + l;
#pragma unroll
        for (int b = 0; b < 8; b++) scr[b * 512 + sbase] = pairsum(acc[b]);
        __syncthreads();

        // ---- stage 2: combine 4 quarters + gates, update c/h for (b2, j2) ----
        if (s2) {
            const float* sb = scr + b2 * 512;
            float gi = p_i + ((sb[      j2] + sb[128 +      j2]) + (sb[256 +      j2] + sb[384 +      j2]));
            float gf = p_f + ((sb[ 32 + j2] + sb[128 + 32 + j2]) + (sb[256 + 32 + j2] + sb[384 + 32 + j2]));
            float gg = p_g + ((sb[ 64 + j2] + sb[128 + 64 + j2]) + (sb[256 + 64 + j2] + sb[384 + 64 + j2]));
            float go = p_o + ((sb[ 96 + j2] + sb[128 + 96 + j2]) + (sb[256 + 96 + j2] + sb[384 + 96 + j2]));
            c = sigf(gf) * c + sigf(gi) * tanhf_(gg);
            float h = sigf(go) * tanhf_(c);

            g_hout[(((size_t)dir * 64 + bg) * L + pos) * 256 + rank * 32 + j2] = h;

            if (s + 1 < L) {                   // deliver h to all 8 CTAs' next buffer
                uint32_t dst = dstbase + (uint32_t)((p ^ 1) * 8192);
                uint32_t mb  = mb_s + (uint32_t)((p ^ 1) * 8);
#pragma unroll
                for (int r = 0; r < 8; r++) {
                    uint32_t ra, rm;
                    asm volatile("mapa.shared::cluster.u32 %0, %1, %2;" : "=r"(ra) : "r"(dst), "r"(r));
                    asm volatile("mapa.shared::cluster.u32 %0, %1, %2;" : "=r"(rm) : "r"(mb), "r"(r));
                    st_async_f32(ra, h, rm);
                }
            }
        }
        __syncthreads();                       // protect scr before next stage-1 overwrite
        p ^= 1;
    }
    cluster_sync();                            // exit safety: no DSMEM traffic in flight
}

// ---------------- K4: final linear (B*L, 512) @ (512, 80) + bias ----------------
#define SW 514
#define ROWS_LIN 24
__global__ void __launch_bounds__(192, 1)
k_lin(const float* __restrict__ linw, const float* __restrict__ linb,
      float* __restrict__ out, int L, int R) {
    extern __shared__ float sm[];
    float* sw = sm;               // [80][SW]
    float* sh = sm + 80 * SW;     // [ROWS_LIN][SW]
    int tid = threadIdx.x;
    int r0g = blockIdx.x * ROWS_LIN;

    for (int i = tid; i < 80 * 256; i += 192) {
        int m = i >> 8, k = (i & 255) * 2;
        float2 v = *(const float2*)(linw + m * 512 + k);
        *(float2*)(sw + m * SW + k) = v;
    }
    for (int i = tid; i < ROWS_LIN * 128; i += 192) {
        int rl = i >> 7, k = (i & 127) * 4;
        int rg = r0g + rl;
        float4 v = make_float4(0.f, 0.f, 0.f, 0.f);
        if (rg < R) {
            int b = rg / L, pos = rg % L;
            int d = k >> 8, j = k & 255;
            v = *(const float4*)(g_hout + (((size_t)d * 64 + b) * L + pos) * 256 + j);
        }
        *(float2*)(sh + rl * SW + k)     = make_float2(v.x, v.y);
        *(float2*)(sh + rl * SW + k + 2) = make_float2(v.z, v.w);
    }
    __syncthreads();

    int mg = tid & 15, rp = tid >> 4;   // 16 m-groups x 12 row-pairs
    int ra = rp * 2, rb = rp * 2 + 1;
    ull a0[5], a1[5];
#pragma unroll
    for (int i = 0; i < 5; i++) { a0[i] = 0ull; a1[i] = 0ull; }
#pragma unroll 8
    for (int kp = 0; kp < 256; kp++) {
        int k = kp * 2;
        ull h0 = *(const ull*)(sh + ra * SW + k);
        ull h1 = *(const ull*)(sh + rb * SW + k);
#pragma unroll
        for (int i = 0; i < 5; i++) {
            ull wv = *(const ull*)(sw + (mg + 16 * i) * SW + k);
            a0[i] = fma2(wv, h0, a0[i]);
            a1[i] = fma2(wv, h1, a1[i]);
        }
    }
#pragma unroll
    for (int i = 0; i < 5; i++) {
        int m = mg + 16 * i;
        float bm = linb[m];
        int rga = r0g + ra, rgb = r0g + rb;
        if (rga < R) out[(size_t)rga * MEL_ + m] = pairsum(a0[i]) + bm;
        if (rgb < R) out[(size_t)rgb * MEL_ + m] = pairsum(a1[i]) + bm;
    }
}

// ---------------- launch ----------------
extern "C" void kernel_launch(void* const* d_in, const int* in_sizes, int n_in,
                              void* d_out, int out_size) {
    const int*   x     = (const int*)  d_in[0];
    const float* embed = (const float*)d_in[1];
    const float* dpw   = (const float*)d_in[2];
    const float* dpb   = (const float*)d_in[3];
    const float* wihf  = (const float*)d_in[4];
    const float* whhf  = (const float*)d_in[5];
    const float* bihf  = (const float*)d_in[6];
    const float* bhhf  = (const float*)d_in[7];
    const float* wihb  = (const float*)d_in[8];
    const float* whhb  = (const float*)d_in[9];
    const float* bihb  = (const float*)d_in[10];
    const float* bhhb  = (const float*)d_in[11];
    const float* linw  = (const float*)d_in[12];
    const float* linb  = (const float*)d_in[13];
    float* out = (float*)d_out;

    int L = out_size / (B_ * MEL_);
    if (L > LMAX_) L = LMAX_;
    int R = B_ * L;

    k_durtab<<<1, 256>>>(embed, dpw, dpb);
    k_expand<<<B_, T_>>>(x);
    k_proj<<<dim3(257, 2, 1), 256>>>(embed, wihf, bihf, bhhf, wihb, bihb, bhhb);
    k_lstm<<<128, 512>>>(whhf, whhb, L);

    int smem = 104 * SW * 4;   // 213,824 B
    cudaFuncSetAttribute(k_lin, cudaFuncAttributeMaxDynamicSharedMemorySize, smem);
    k_lin<<<(R + ROWS_LIN - 1) / ROWS_LIN, 192, smem>>>(linw, linb, out, L, R);
}

// round 5
// speedup vs baseline: 1.1543x; 1.0337x over previous
#include <cuda_runtime.h>
#include <cstdint>
#include <cstdio>

#define B_ 64
#define T_ 512
#define EMB_ 128
#define HID_ 256
#define MEL_ 80
#define LMAX_ 2048

typedef unsigned long long ull;

// ---------------- static device scratch (no allocations allowed) ----------------
__device__ int   g_durTab[256];
__device__ int   g_tok[B_ * LMAX_];                 // vocab id per expanded pos, 256 = pad
__device__ float g_projE[2 * 257 * 1024];           // Wih@embed[v] + bih + bhh  (entry 256 = bias only)
__device__ float g_hout[2ull * B_ * LMAX_ * HID_];  // [dir][b][pos][256]

// ---------------- helpers ----------------
__device__ __forceinline__ ull fma2(ull a, ull b, ull c) {   // packed: d = a*b + c (2x f32)
    ull d;
    asm("fma.rn.f32x2 %0, %1, %2, %3;" : "=l"(d) : "l"(a), "l"(b), "l"(c));
    return d;
}
__device__ __forceinline__ float pairsum(ull v) {
    float x, y;
    asm("mov.b64 {%0, %1}, %2;" : "=f"(x), "=f"(y) : "l"(v));
    return x + y;
}
__device__ __forceinline__ float sigf(float x)  { return __fdividef(1.f, 1.f + __expf(-x)); }
__device__ __forceinline__ float tanhf_(float x){ return 1.f - __fdividef(2.f, 1.f + __expf(2.f * x)); }

__device__ __forceinline__ void cluster_sync() {
    asm volatile("barrier.cluster.arrive.aligned;" ::: "memory");
    asm volatile("barrier.cluster.wait.aligned;" ::: "memory");
}
__device__ __forceinline__ void mbar_init(uint32_t a, uint32_t cnt) {
    asm volatile("mbarrier.init.shared.b64 [%0], %1;" :: "r"(a), "r"(cnt) : "memory");
}
__device__ __forceinline__ void mbar_arrive_expect(uint32_t a, uint32_t tx) {
    asm volatile("mbarrier.arrive.expect_tx.shared.b64 _, [%0], %1;" :: "r"(a), "r"(tx) : "memory");
}
__device__ __forceinline__ void mbar_wait(uint32_t a, uint32_t par) {
    asm volatile(
        "{\n\t"
        ".reg .pred P;\n\t"
        "W%=:\n\t"
        "mbarrier.try_wait.parity.acquire.cluster.shared::cta.b64 P, [%0], %1;\n\t"
        "@P bra D%=;\n\t"
        "bra W%=;\n\t"
        "D%=:\n\t"
        "}"
        :: "r"(a), "r"(par) : "memory");
}
__device__ __forceinline__ void s2s_bulk(uint32_t dst, uint32_t src, uint32_t bytes, uint32_t rmbar) {
    asm volatile("cp.async.bulk.shared::cluster.shared::cta.mbarrier::complete_tx::bytes [%0], [%1], %2, [%3];"
                 :: "r"(dst), "r"(src), "r"(bytes), "r"(rmbar) : "memory");
}

// ---------------- K1a: per-vocab duration table ----------------
__global__ void k_durtab(const float* __restrict__ embed, const float* __restrict__ dpw,
                         const float* __restrict__ dpb) {
    __shared__ float w[EMB_];
    int t = threadIdx.x;           // 0..255 = vocab id
    if (t < EMB_) w[t] = dpw[t];
    __syncthreads();
    const float* e = embed + t * EMB_;
    double acc = (double)dpb[0];
#pragma unroll 8
    for (int k = 0; k < EMB_; k++) acc += (double)e[k] * (double)w[k];
    float d = (float)acc;
    if (d < 0.f) d = 0.f;
    g_durTab[t] = (int)floorf(d) + 1;
}

// ---------------- K1b: per-batch scan + token scatter ----------------
__global__ void k_expand(const int* __restrict__ x) {
    __shared__ int s[T_];
    int b = blockIdx.x, t = threadIdx.x;
    int tokid = x[b * T_ + t];
    s[t] = g_durTab[tokid];
    __syncthreads();
    for (int off = 1; off < T_; off <<= 1) {
        int v = s[t];
        int a = (t >= off) ? s[t - off] : 0;
        __syncthreads();
        s[t] = v + a;
        __syncthreads();
    }
    for (int p = t; p < LMAX_; p += T_) g_tok[b * LMAX_ + p] = 256;   // pad
    __syncthreads();
    int st = t ? s[t - 1] : 0;
    int en = s[t];
    if (en > LMAX_) en = LMAX_;
    for (int p = st; p < en; p++) g_tok[b * LMAX_ + p] = tokid;
}

// ---------------- K2: per-vocab input-projection tables (weights touched once) ----------------
// grid (8 rowgroups, 2 dirs), 256 threads. Thread pair (row, k-half); all 257 embeds in smem.
__global__ void __launch_bounds__(256, 1)
k_proj(const float* __restrict__ embed,
       const float* __restrict__ wih_f, const float* __restrict__ bih_f, const float* __restrict__ bhh_f,
       const float* __restrict__ wih_b, const float* __restrict__ bih_b, const float* __restrict__ bhh_b) {
    extern __shared__ float se[];               // [257][128]
    int dir = blockIdx.y;
    const float* wih = dir ? wih_b : wih_f;
    const float* bi  = dir ? bih_b : bih_f;
    const float* bh  = dir ? bhh_b : bhh_f;
    int tid = threadIdx.x;
    for (int i = tid; i < 257 * 128; i += 256)
        se[i] = (i < 256 * 128) ? embed[i] : 0.f;
    __syncthreads();

    int rloc = tid >> 1, hf = tid & 1;          // 128 rows per block, 2 k-halves
    int r = blockIdx.x * 128 + rloc;
    // weight half-row -> regs (touched once)
    ull wreg[32];
    const ulonglong2* wp = (const ulonglong2*)(wih + r * EMB_ + hf * 64);
#pragma unroll
    for (int i = 0; i < 16; i++) { ulonglong2 u = wp[i]; wreg[2 * i] = u.x; wreg[2 * i + 1] = u.y; }
    float bsum = bi[r] + bh[r];

    for (int v = 0; v < 257; v++) {
        const float* ev = se + v * 128 + hf * 64;
        ull acc = 0ull;
#pragma unroll
        for (int i = 0; i < 16; i++) {
            ulonglong2 e2 = *(const ulonglong2*)(ev + i * 4);
            acc = fma2(wreg[2 * i], e2.x, acc);
            acc = fma2(wreg[2 * i + 1], e2.y, acc);
        }
        float part = pairsum(acc);
        float other = __shfl_xor_sync(0xFFFFFFFFu, part, 1);
        if (hf == 0)
            g_projE[(dir * 257 + v) * 1024 + r] = part + other + bsum;
    }
}

// ---------------- K3: persistent cluster biLSTM ----------------
// 16 clusters x 8 CTAs x 512 threads. cluster = (dir, batch-group of 8).
// CTA rank owns 32-wide hidden slice (128 gate rows). Warp = (gate g, K-quarter kq), lane = j.
// h layout: [phase][rank][b][32] so each CTA's produced slice is one contiguous 1KB tile,
// exchanged with 8 cp.async.bulk s2s copies (complete_tx on peers' mbar).
__global__ void __cluster_dims__(8, 1, 1) __launch_bounds__(512, 1)
k_lstm(const float* __restrict__ whh_f, const float* __restrict__ whh_b, int L) {
    extern __shared__ __align__(16) float smem[];
    float* hbuf = smem;                  // [2][8rank][8b][32j]  = 4096 f
    float* scr  = smem + 4096;           // [2][8b][512]         = 8192 f
    float* stg  = smem + 4096 + 8192;    // [2][8b][32j]         = 512 f
    ull*   mbars = (ull*)(smem + 4096 + 8192 + 512);   // [2]

    int tid = threadIdx.x;
    int w = tid >> 5, l = tid & 31;
    int bx = blockIdx.x;
    int rank = bx & 7;            // hidden slice
    int cid = bx >> 3;
    int dir = cid >> 3;           // 0 = fwd, 1 = bwd
    int bbase = (cid & 7) * 8;
    const float* whh = dir ? whh_b : whh_f;

    // stage-1 identity: gate g = w>>2 (0..3), K-quarter kq = w&3, row j = l
    int g = w >> 2, kq = w & 3;
    const ulonglong2* wp =
        (const ulonglong2*)(whh + ((g * 256 + rank * 32 + l) * 256 + kq * 64));
    ull wr[32];                    // 64 floats of Whh, step-invariant
#pragma unroll
    for (int i = 0; i < 16; i++) { ulonglong2 u = wp[i]; wr[2 * i] = u.x; wr[2 * i + 1] = u.y; }

    for (int i = tid; i < 4096; i += 512) hbuf[i] = 0.f;

    uint32_t hb_s = (uint32_t)__cvta_generic_to_shared(hbuf);
    uint32_t st_s = (uint32_t)__cvta_generic_to_shared(stg);
    uint32_t mb_s = (uint32_t)__cvta_generic_to_shared(mbars);
    if (tid == 0) {
        mbar_init(mb_s, 1);
        mbar_init(mb_s + 8, 1);
        asm volatile("fence.mbarrier_init.release.cluster;" ::: "memory");
        mbar_arrive_expect(mb_s, 8192);        // pre-arm both phases' first use
        mbar_arrive_expect(mb_s + 8, 8192);
    }
    __syncthreads();
    cluster_sync();                            // init + arm + zeroed hbuf visible cluster-wide

    // stage-2 identity: batch b2 = tid>>5, hidden j2 = tid&31 (warps 0..7)
    bool s2 = tid < 256;
    int b2 = tid >> 5, j2 = tid & 31;
    int bg = bbase + b2;
    float c = 0.f;

    unsigned par0 = 0, par1 = 0;
    int p = 0;
    for (int s = 0; s < L; s++) {
        int pos = dir ? (L - 1 - s) : s;
        // early gathers for stage 2 (latency overlapped with wait + stage 1)
        float p_i = 0.f, p_f = 0.f, p_g = 0.f, p_o = 0.f;
        if (s2) {
            int tok = g_tok[bg * LMAX_ + pos];
            const float* pe = g_projE + (dir * 257 + tok) * 1024 + rank * 32 + j2;
            p_i = pe[0]; p_f = pe[256]; p_g = pe[512]; p_o = pe[768];
        }
        if (s > 0) {
            uint32_t mb = mb_s + (uint32_t)(p * 8);
            unsigned par = p ? par1 : par0;
            mbar_wait(mb, par);                // all 8 x 1KB slices delivered for this phase
            if (p) par1 ^= 1; else par0 ^= 1;
            if (tid == 0) mbar_arrive_expect(mb, 8192);   // rearm 2 steps ahead (race-free)
        }

        // ---- stage 1: 64-long quarter-dot for my gate row, 8 batch rows ----
        ull acc[8];
#pragma unroll
        for (int b = 0; b < 8; b++) acc[b] = 0ull;
#pragma unroll
        for (int h2 = 0; h2 < 2; h2++) {
            const float* hb = hbuf + p * 2048 + (2 * kq + h2) * 256;   // [b][32]
#pragma unroll
            for (int i = 0; i < 8; i++) {
#pragma unroll
                for (int b = 0; b < 8; b++) {
                    ulonglong2 hv = *(const ulonglong2*)(hb + b * 32 + i * 4);
                    int wi = (h2 * 8 + i) * 2;
                    acc[b] = fma2(wr[wi], hv.x, acc[b]);
                    acc[b] = fma2(wr[wi + 1], hv.y, acc[b]);
                }
            }
        }
        float* sc = scr + p * 4096;
        int sbase = kq * 128 + g * 32 + l;
#pragma unroll
        for (int b = 0; b < 8; b++) sc[b * 512 + sbase] = pairsum(acc[b]);

        if (!s2) {
            asm volatile("bar.arrive 1, 512;" ::: "memory");   // producers don't block
        } else {
            asm volatile("bar.sync 1, 512;" ::: "memory");
            // ---- stage 2: combine 4 quarters + gates, update c/h for (b2, j2) ----
            const float* sb = sc + b2 * 512;
            float gi = p_i + ((sb[      j2] + sb[128 +      j2]) + (sb[256 +      j2] + sb[384 +      j2]));
            float gf = p_f + ((sb[ 32 + j2] + sb[128 + 32 + j2]) + (sb[256 + 32 + j2] + sb[384 + 32 + j2]));
            float gg = p_g + ((sb[ 64 + j2] + sb[128 + 64 + j2]) + (sb[256 + 64 + j2] + sb[384 + 64 + j2]));
            float go = p_o + ((sb[ 96 + j2] + sb[128 + 96 + j2]) + (sb[256 + 96 + j2] + sb[384 + 96 + j2]));
            c = sigf(gf) * c + sigf(gi) * tanhf_(gg);
            float h = sigf(go) * tanhf_(c);

            g_hout[(((size_t)dir * 64 + bg) * L + pos) * 256 + rank * 32 + j2] = h;

            if (s + 1 < L) {
                stg[p * 256 + b2 * 32 + j2] = h;               // contiguous 1KB tile
                asm volatile("bar.sync 2, 256;" ::: "memory"); // stage-2 warps only
                if (tid < 8) {                                 // 8 bulk copies, one per peer
                    asm volatile("fence.proxy.async.shared::cta;" ::: "memory");
                    uint32_t dst = hb_s + (uint32_t)(((p ^ 1) * 2048 + rank * 256) * 4);
                    uint32_t mb  = mb_s + (uint32_t)((p ^ 1) * 8);
                    uint32_t src = st_s + (uint32_t)(p * 1024);
                    uint32_t ra, rm;
                    asm volatile("mapa.shared::cluster.u32 %0, %1, %2;" : "=r"(ra) : "r"(dst), "r"(tid));
                    asm volatile("mapa.shared::cluster.u32 %0, %1, %2;" : "=r"(rm) : "r"(mb), "r"(tid));
                    s2s_bulk(ra, src, 1024, rm);
                }
            }
        }
        p ^= 1;
    }
    cluster_sync();                            // exit safety
}

// ---------------- K4: final linear (B*L, 512) @ (512, 80) + bias ----------------
#define SW 514
#define ROWS_LIN 24
__global__ void __launch_bounds__(192, 1)
k_lin(const float* __restrict__ linw, const float* __restrict__ linb,
      float* __restrict__ out, int L, int R) {
    extern __shared__ float sm[];
    float* sw = sm;               // [80][SW]
    float* sh = sm + 80 * SW;     // [ROWS_LIN][SW]
    int tid = threadIdx.x;
    int r0g = blockIdx.x * ROWS_LIN;

    for (int i = tid; i < 80 * 256; i += 192) {
        int m = i >> 8, k = (i & 255) * 2;
        float2 v = *(const float2*)(linw + m * 512 + k);
        *(float2*)(sw + m * SW + k) = v;
    }
    for (int i = tid; i < ROWS_LIN * 128; i += 192) {
        int rl = i >> 7, k = (i & 127) * 4;
        int rg = r0g + rl;
        float4 v = make_float4(0.f, 0.f, 0.f, 0.f);
        if (rg < R) {
            int b = rg / L, pos = rg % L;
            int d = k >> 8, j = k & 255;
            v = *(const float4*)(g_hout + (((size_t)d * 64 + b) * L + pos) * 256 + j);
        }
        *(float2*)(sh + rl * SW + k)     = make_float2(v.x, v.y);
        *(float2*)(sh + rl * SW + k + 2) = make_float2(v.z, v.w);
    }
    __syncthreads();

    int mg = tid & 15, rp = tid >> 4;   // 16 m-groups x 12 row-pairs
    int ra = rp * 2, rb = rp * 2 + 1;
    ull a0[5], a1[5];
#pragma unroll
    for (int i = 0; i < 5; i++) { a0[i] = 0ull; a1[i] = 0ull; }
#pragma unroll 8
    for (int kp = 0; kp < 256; kp++) {
        int k = kp * 2;
        ull h0 = *(const ull*)(sh + ra * SW + k);
        ull h1 = *(const ull*)(sh + rb * SW + k);
#pragma unroll
        for (int i = 0; i < 5; i++) {
            ull wv = *(const ull*)(sw + (mg + 16 * i) * SW + k);
            a0[i] = fma2(wv, h0, a0[i]);
            a1[i] = fma2(wv, h1, a1[i]);
        }
    }
#pragma unroll
    for (int i = 0; i < 5; i++) {
        int m = mg + 16 * i;
        float bm = linb[m];
        int rga = r0g + ra, rgb = r0g + rb;
        if (rga < R) out[(size_t)rga * MEL_ + m] = pairsum(a0[i]) + bm;
        if (rgb < R) out[(size_t)rgb * MEL_ + m] = pairsum(a1[i]) + bm;
    }
}

// ---------------- launch ----------------
extern "C" void kernel_launch(void* const* d_in, const int* in_sizes, int n_in,
                              void* d_out, int out_size) {
    const int*   x     = (const int*)  d_in[0];
    const float* embed = (const float*)d_in[1];
    const float* dpw   = (const float*)d_in[2];
    const float* dpb   = (const float*)d_in[3];
    const float* wihf  = (const float*)d_in[4];
    const float* whhf  = (const float*)d_in[5];
    const float* bihf  = (const float*)d_in[6];
    const float* bhhf  = (const float*)d_in[7];
    const float* wihb  = (const float*)d_in[8];
    const float* whhb  = (const float*)d_in[9];
    const float* bihb  = (const float*)d_in[10];
    const float* bhhb  = (const float*)d_in[11];
    const float* linw  = (const float*)d_in[12];
    const float* linb  = (const float*)d_in[13];
    float* out = (float*)d_out;

    int L = out_size / (B_ * MEL_);
    if (L > LMAX_) L = LMAX_;
    int R = B_ * L;

    k_durtab<<<1, 256>>>(embed, dpw, dpb);
    k_expand<<<B_, T_>>>(x);

    int smem_proj = 257 * 128 * 4;                 // 131,584 B
    cudaFuncSetAttribute(k_proj, cudaFuncAttributeMaxDynamicSharedMemorySize, smem_proj);
    k_proj<<<dim3(8, 2, 1), 256, smem_proj>>>(embed, wihf, bihf, bhhf, wihb, bihb, bhhb);

    int smem_lstm = (4096 + 8192 + 512) * 4 + 16;  // 51,216 B
    cudaFuncSetAttribute(k_lstm, cudaFuncAttributeMaxDynamicSharedMemorySize, smem_lstm);
    k_lstm<<<128, 512, smem_lstm>>>(whhf, whhb, L);

    int smem_lin = 104 * SW * 4;                   // 213,824 B
    cudaFuncSetAttribute(k_lin, cudaFuncAttributeMaxDynamicSharedMemorySize, smem_lin);
    k_lin<<<(R + ROWS_LIN - 1) / ROWS_LIN, 192, smem_lin>>>(linw, linb, out, L, R);
}

// round 6
// speedup vs baseline: 1.1791x; 1.0215x over previous
#include <cuda_runtime.h>
#include <cstdint>
#include <cstdio>

#define B_ 64
#define T_ 512
#define EMB_ 128
#define HID_ 256
#define MEL_ 80
#define LMAX_ 2048

typedef unsigned long long ull;

// ---------------- static device scratch (no allocations allowed) ----------------
__device__ int   g_durTab[256];
__device__ int   g_tok[B_ * LMAX_];                 // vocab id per expanded pos, 256 = pad
__device__ float g_projE[2 * 257 * 1024];           // Wih@embed[v] + bih + bhh  (entry 256 = bias only)
__device__ float g_hout[2ull * B_ * LMAX_ * HID_];  // [dir][b][pos][256]

// ---------------- helpers ----------------
__device__ __forceinline__ ull fma2(ull a, ull b, ull c) {   // packed: d = a*b + c (2x f32)
    ull d;
    asm("fma.rn.f32x2 %0, %1, %2, %3;" : "=l"(d) : "l"(a), "l"(b), "l"(c));
    return d;
}
__device__ __forceinline__ float pairsum(ull v) {
    float x, y;
    asm("mov.b64 {%0, %1}, %2;" : "=f"(x), "=f"(y) : "l"(v));
    return x + y;
}
__device__ __forceinline__ float sigf(float x)  { return __fdividef(1.f, 1.f + __expf(-x)); }
__device__ __forceinline__ float tanhf_(float x){ return 1.f - __fdividef(2.f, 1.f + __expf(2.f * x)); }

__device__ __forceinline__ void cluster_sync() {
    asm volatile("barrier.cluster.arrive.aligned;" ::: "memory");
    asm volatile("barrier.cluster.wait.aligned;" ::: "memory");
}
__device__ __forceinline__ void mbar_init(uint32_t a, uint32_t cnt) {
    asm volatile("mbarrier.init.shared.b64 [%0], %1;" :: "r"(a), "r"(cnt) : "memory");
}
__device__ __forceinline__ void mbar_arrive_expect(uint32_t a, uint32_t tx) {
    asm volatile("mbarrier.arrive.expect_tx.shared.b64 _, [%0], %1;" :: "r"(a), "r"(tx) : "memory");
}
__device__ __forceinline__ void mbar_wait(uint32_t a, uint32_t par) {
    asm volatile(
        "{\n\t"
        ".reg .pred P;\n\t"
        "W%=:\n\t"
        "mbarrier.try_wait.parity.acquire.cluster.shared::cta.b64 P, [%0], %1, 0x989680;\n\t"
        "@P bra D%=;\n\t"
        "bra W%=;\n\t"
        "D%=:\n\t"
        "}"
        :: "r"(a), "r"(par) : "memory");
}
__device__ __forceinline__ void s2s_bulk(uint32_t dst, uint32_t src, uint32_t bytes, uint32_t rmbar) {
    asm volatile("cp.async.bulk.shared::cluster.shared::cta.mbarrier::complete_tx::bytes [%0], [%1], %2, [%3];"
                 :: "r"(dst), "r"(src), "r"(bytes), "r"(rmbar) : "memory");
}

// ---------------- K1a: per-vocab duration table ----------------
__global__ void k_durtab(const float* __restrict__ embed, const float* __restrict__ dpw,
                         const float* __restrict__ dpb) {
    __shared__ float w[EMB_];
    int t = threadIdx.x;           // 0..255 = vocab id
    if (t < EMB_) w[t] = dpw[t];
    __syncthreads();
    const float* e = embed + t * EMB_;
    double acc = (double)dpb[0];
#pragma unroll 8
    for (int k = 0; k < EMB_; k++) acc += (double)e[k] * (double)w[k];
    float d = (float)acc;
    if (d < 0.f) d = 0.f;
    g_durTab[t] = (int)floorf(d) + 1;
}

// ---------------- K1b: per-batch scan + token scatter ----------------
__global__ void k_expand(const int* __restrict__ x) {
    __shared__ int s[T_];
    int b = blockIdx.x, t = threadIdx.x;
    int tokid = x[b * T_ + t];
    s[t] = g_durTab[tokid];
    __syncthreads();
    for (int off = 1; off < T_; off <<= 1) {
        int v = s[t];
        int a = (t >= off) ? s[t - off] : 0;
        __syncthreads();
        s[t] = v + a;
        __syncthreads();
    }
    for (int p = t; p < LMAX_; p += T_) g_tok[b * LMAX_ + p] = 256;   // pad
    __syncthreads();
    int st = t ? s[t - 1] : 0;
    int en = s[t];
    if (en > LMAX_) en = LMAX_;
    for (int p = st; p < en; p++) g_tok[b * LMAX_ + p] = tokid;
}

// ---------------- K2: per-vocab input-projection tables (weights touched once) ----------------
__global__ void __launch_bounds__(256, 1)
k_proj(const float* __restrict__ embed,
       const float* __restrict__ wih_f, const float* __restrict__ bih_f, const float* __restrict__ bhh_f,
       const float* __restrict__ wih_b, const float* __restrict__ bih_b, const float* __restrict__ bhh_b) {
    extern __shared__ float se[];               // [257][128]
    int dir = blockIdx.y;
    const float* wih = dir ? wih_b : wih_f;
    const float* bi  = dir ? bih_b : bih_f;
    const float* bh  = dir ? bhh_b : bhh_f;
    int tid = threadIdx.x;
    for (int i = tid; i < 257 * 128; i += 256)
        se[i] = (i < 256 * 128) ? embed[i] : 0.f;
    __syncthreads();

    int rloc = tid >> 1, hf = tid & 1;          // 128 rows per block, 2 k-halves
    int r = blockIdx.x * 128 + rloc;
    ull wreg[32];
    const ulonglong2* wp = (const ulonglong2*)(wih + r * EMB_ + hf * 64);
#pragma unroll
    for (int i = 0; i < 16; i++) { ulonglong2 u = wp[i]; wreg[2 * i] = u.x; wreg[2 * i + 1] = u.y; }
    float bsum = bi[r] + bh[r];

    for (int v = 0; v < 257; v++) {
        const float* ev = se + v * 128 + hf * 64;
        ull acc = 0ull;
#pragma unroll
        for (int i = 0; i < 16; i++) {
            ulonglong2 e2 = *(const ulonglong2*)(ev + i * 4);
            acc = fma2(wreg[2 * i], e2.x, acc);
            acc = fma2(wreg[2 * i + 1], e2.y, acc);
        }
        float part = pairsum(acc);
        float other = __shfl_xor_sync(0xFFFFFFFFu, part, 1);
        if (hf == 0)
            g_projE[(dir * 257 + v) * 1024 + r] = part + other + bsum;
    }
}

// ---------------- K3: persistent cluster biLSTM, 2 interleaved batch-groups ----------------
// 8 clusters x 8 CTAs x 512 threads. cluster cid: dir = cid>>2, groups (cid&3)*2 + {0,1}.
// CTA rank owns 32-wide hidden slice; weights (64 f/thread) shared by both groups.
// Group A's exchange latency hides under group B's FMA block and vice versa.
__global__ void __cluster_dims__(8, 1, 1) __launch_bounds__(512, 1)
k_lstm(const float* __restrict__ whh_f, const float* __restrict__ whh_b, int L) {
    extern __shared__ __align__(16) float smem[];
    float* hbuf = smem;                    // [grp][ph][rank][b][32] = 8192 f
    float* scr  = smem + 8192;             // [grp][ph][b][512]      = 16384 f
    float* stg  = smem + 8192 + 16384;     // [grp][ph][256]         = 1024 f
    ull*   mbars = (ull*)(smem + 8192 + 16384 + 1024);   // [grp][ph] = 4

    int tid = threadIdx.x;
    int w = tid >> 5, l = tid & 31;
    int bx = blockIdx.x;
    int rank = bx & 7;
    int cid = bx >> 3;
    int dir = cid >> 2;                    // 0 = fwd, 1 = bwd
    int gpair = cid & 3;                   // batch-group pair
    const float* whh = dir ? whh_b : whh_f;

    // stage-1 identity: gate g = w>>2, K-quarter kq = w&3, row j = l
    int g = w >> 2, kq = w & 3;
    const ulonglong2* wp =
        (const ulonglong2*)(whh + ((g * 256 + rank * 32 + l) * 256 + kq * 64));
    ull wr[32];
#pragma unroll
    for (int i = 0; i < 16; i++) { ulonglong2 u = wp[i]; wr[2 * i] = u.x; wr[2 * i + 1] = u.y; }

    for (int i = tid; i < 8192; i += 512) hbuf[i] = 0.f;

    uint32_t hb_s = (uint32_t)__cvta_generic_to_shared(hbuf);
    uint32_t st_s = (uint32_t)__cvta_generic_to_shared(stg);
    uint32_t mb_s = (uint32_t)__cvta_generic_to_shared(mbars);
    if (tid == 0) {
#pragma unroll
        for (int q = 0; q < 4; q++) mbar_init(mb_s + 8 * q, 1);
        asm volatile("fence.mbarrier_init.release.cluster;" ::: "memory");
#pragma unroll
        for (int q = 0; q < 4; q++) mbar_arrive_expect(mb_s + 8 * q, 8192);
    }
    __syncthreads();
    cluster_sync();

    bool s2 = tid < 256;
    int b2 = tid >> 5, j2 = tid & 31;
    float cst[2] = {0.f, 0.f};             // cell state per group
    unsigned parr = 0;                     // parity bits: bit (grp*2+p)

    int p = 0;
    for (int s = 0; s < L; s++) {
        int pos = dir ? (L - 1 - s) : s;
#pragma unroll
        for (int grp = 0; grp < 2; grp++) {
            int bg = (gpair * 2 + grp) * 8 + b2;
            // early gathers for stage 2
            float p_i = 0.f, p_f = 0.f, p_g = 0.f, p_o = 0.f;
            if (s2) {
                int tok = g_tok[bg * LMAX_ + pos];
                const float* pe = g_projE + (dir * 257 + tok) * 1024 + rank * 32 + j2;
                p_i = pe[0]; p_f = pe[256]; p_g = pe[512]; p_o = pe[768];
            }
            if (s > 0) {
                int q = grp * 2 + p;
                mbar_wait(mb_s + 8 * q, (parr >> q) & 1);
                parr ^= 1u << q;
                if (tid == 0) mbar_arrive_expect(mb_s + 8 * q, 8192);  // rearm 2 steps ahead
            }

            // ---- stage 1: quarter-dot for my gate row, 8 batch rows ----
            ull acc[8];
#pragma unroll
            for (int b = 0; b < 8; b++) acc[b] = 0ull;
#pragma unroll
            for (int h2 = 0; h2 < 2; h2++) {
                const float* hb = hbuf + grp * 4096 + p * 2048 + (2 * kq + h2) * 256;
#pragma unroll
                for (int i = 0; i < 8; i++) {
#pragma unroll
                    for (int b = 0; b < 8; b++) {
                        ulonglong2 hv = *(const ulonglong2*)(hb + b * 32 + i * 4);
                        int wi = (h2 * 8 + i) * 2;
                        acc[b] = fma2(wr[wi], hv.x, acc[b]);
                        acc[b] = fma2(wr[wi + 1], hv.y, acc[b]);
                    }
                }
            }
            float* sc = scr + grp * 8192 + p * 4096;
            int sbase = kq * 128 + g * 32 + l;
#pragma unroll
            for (int b = 0; b < 8; b++) sc[b * 512 + sbase] = pairsum(acc[b]);

            if (!s2) {
                asm volatile("bar.arrive %0, 512;" :: "r"(1 + grp) : "memory");  // producers run ahead
            } else {
                asm volatile("bar.sync %0, 512;" :: "r"(1 + grp) : "memory");
                // ---- stage 2: gates + state update for (grp, b2, j2) ----
                const float* sb = sc + b2 * 512;
                float gi = p_i + ((sb[      j2] + sb[128 +      j2]) + (sb[256 +      j2] + sb[384 +      j2]));
                float gf = p_f + ((sb[ 32 + j2] + sb[128 + 32 + j2]) + (sb[256 + 32 + j2] + sb[384 + 32 + j2]));
                float gg = p_g + ((sb[ 64 + j2] + sb[128 + 64 + j2]) + (sb[256 + 64 + j2] + sb[384 + 64 + j2]));
                float go = p_o + ((sb[ 96 + j2] + sb[128 + 96 + j2]) + (sb[256 + 96 + j2] + sb[384 + 96 + j2]));
                float c = sigf(gf) * cst[grp] + sigf(gi) * tanhf_(gg);
                cst[grp] = c;
                float h = sigf(go) * tanhf_(c);

                g_hout[(((size_t)dir * 64 + bg) * L + pos) * 256 + rank * 32 + j2] = h;

                if (s + 1 < L) {
                    stg[grp * 512 + p * 256 + b2 * 32 + j2] = h;     // contiguous 1KB tile
                    asm volatile("bar.sync %0, 256;" :: "r"(3 + grp) : "memory");
                    if (tid < 8) {
                        asm volatile("fence.proxy.async.shared::cta;" ::: "memory");
                        uint32_t dst = hb_s + (uint32_t)((grp * 4096 + (p ^ 1) * 2048 + rank * 256) * 4);
                        uint32_t mb  = mb_s + (uint32_t)((grp * 2 + (p ^ 1)) * 8);
                        uint32_t src = st_s + (uint32_t)((grp * 512 + p * 256) * 4);
                        uint32_t ra, rm;
                        asm volatile("mapa.shared::cluster.u32 %0, %1, %2;" : "=r"(ra) : "r"(dst), "r"(tid));
                        asm volatile("mapa.shared::cluster.u32 %0, %1, %2;" : "=r"(rm) : "r"(mb), "r"(tid));
                        s2s_bulk(ra, src, 1024, rm);
                    }
                }
            }
        }
        p ^= 1;
    }
    cluster_sync();                        // exit safety
}

// ---------------- K4: final linear (B*L, 512) @ (512, 80) + bias ----------------
#define SW 514
#define ROWS_LIN 24
__global__ void __launch_bounds__(192, 1)
k_lin(const float* __restrict__ linw, const float* __restrict__ linb,
      float* __restrict__ out, int L, int R) {
    extern __shared__ float sm[];
    float* sw = sm;               // [80][SW]
    float* sh = sm + 80 * SW;     // [ROWS_LIN][SW]
    int tid = threadIdx.x;
    int r0g = blockIdx.x * ROWS_LIN;

    for (int i = tid; i < 80 * 256; i += 192) {
        int m = i >> 8, k = (i & 255) * 2;
        float2 v = *(const float2*)(linw + m * 512 + k);
        *(float2*)(sw + m * SW + k) = v;
    }
    for (int i = tid; i < ROWS_LIN * 128; i += 192) {
        int rl = i >> 7, k = (i & 127) * 4;
        int rg = r0g + rl;
        float4 v = make_float4(0.f, 0.f, 0.f, 0.f);
        if (rg < R) {
            int b = rg / L, pos = rg % L;
            int d = k >> 8, j = k & 255;
            v = *(const float4*)(g_hout + (((size_t)d * 64 + b) * L + pos) * 256 + j);
        }
        *(float2*)(sh + rl * SW + k)     = make_float2(v.x, v.y);
        *(float2*)(sh + rl * SW + k + 2) = make_float2(v.z, v.w);
    }
    __syncthreads();

    int mg = tid & 15, rp = tid >> 4;   // 16 m-groups x 12 row-pairs
    int ra = rp * 2, rb = rp * 2 + 1;
    ull a0[5], a1[5];
#pragma unroll
    for (int i = 0; i < 5; i++) { a0[i] = 0ull; a1[i] = 0ull; }
#pragma unroll 8
    for (int kp = 0; kp < 256; kp++) {
        int k = kp * 2;
        ull h0 = *(const ull*)(sh + ra * SW + k);
        ull h1 = *(const ull*)(sh + rb * SW + k);
#pragma unroll
        for (int i = 0; i < 5; i++) {
            ull wv = *(const ull*)(sw + (mg + 16 * i) * SW + k);
            a0[i] = fma2(wv, h0, a0[i]);
            a1[i] = fma2(wv, h1, a1[i]);
        }
    }
#pragma unroll
    for (int i = 0; i < 5; i++) {
        int m = mg + 16 * i;
        float bm = linb[m];
        int rga = r0g + ra, rgb = r0g + rb;
        if (rga < R) out[(size_t)rga * MEL_ + m] = pairsum(a0[i]) + bm;
        if (rgb < R) out[(size_t)rgb * MEL_ + m] = pairsum(a1[i]) + bm;
    }
}

// ---------------- launch ----------------
extern "C" void kernel_launch(void* const* d_in, const int* in_sizes, int n_in,
                              void* d_out, int out_size) {
    const int*   x     = (const int*)  d_in[0];
    const float* embed = (const float*)d_in[1];
    const float* dpw   = (const float*)d_in[2];
    const float* dpb   = (const float*)d_in[3];
    const float* wihf  = (const float*)d_in[4];
    const float* whhf  = (const float*)d_in[5];
    const float* bihf  = (const float*)d_in[6];
    const float* bhhf  = (const float*)d_in[7];
    const float* wihb  = (const float*)d_in[8];
    const float* whhb  = (const float*)d_in[9];
    const float* bihb  = (const float*)d_in[10];
    const float* bhhb  = (const float*)d_in[11];
    const float* linw  = (const float*)d_in[12];
    const float* linb  = (const float*)d_in[13];
    float* out = (float*)d_out;

    int L = out_size / (B_ * MEL_);
    if (L > LMAX_) L = LMAX_;
    int R = B_ * L;

    k_durtab<<<1, 256>>>(embed, dpw, dpb);
    k_expand<<<B_, T_>>>(x);

    int smem_proj = 257 * 128 * 4;                 // 131,584 B
    cudaFuncSetAttribute(k_proj, cudaFuncAttributeMaxDynamicSharedMemorySize, smem_proj);
    k_proj<<<dim3(8, 2, 1), 256, smem_proj>>>(embed, wihf, bihf, bhhf, wihb, bihb, bhhb);

    int smem_lstm = (8192 + 16384 + 1024) * 4 + 32;  // 102,432 B
    cudaFuncSetAttribute(k_lstm, cudaFuncAttributeMaxDynamicSharedMemorySize, smem_lstm);
    k_lstm<<<64, 512, smem_lstm>>>(whhf, whhb, L);

    int smem_lin = 104 * SW * 4;                   // 213,824 B
    cudaFuncSetAttribute(k_lin, cudaFuncAttributeMaxDynamicSharedMemorySize, smem_lin);
    k_lin<<<(R + ROWS_LIN - 1) / ROWS_LIN, 192, smem_lin>>>(linw, linb, out, L, R);
}

// round 8
// speedup vs baseline: 1.7810x; 1.5105x over previous
#include <cuda_runtime.h>
#include <cuda_bf16.h>
#include <cstdint>
#include <cstdio>

#define B_ 64
#define T_ 512
#define EMB_ 128
#define HID_ 256
#define MEL_ 80
#define LMAX_ 2048

typedef unsigned long long ull;

// ---------------- static device scratch ----------------
__device__ int   g_durTab[256];
__device__ int   g_tok[B_ * LMAX_];                 // vocab id per expanded pos, 256 = pad
__device__ float g_projE[2 * 257 * 1024];           // Wih@embed[v] + bih + bhh  (entry 256 = bias only)
__device__ float g_hout[2ull * B_ * LMAX_ * HID_];  // [dir][b][pos][256]

// ---------------- generic helpers ----------------
__device__ __forceinline__ ull fma2(ull a, ull b, ull c) {
    ull d;
    asm("fma.rn.f32x2 %0, %1, %2, %3;" : "=l"(d) : "l"(a), "l"(b), "l"(c));
    return d;
}
__device__ __forceinline__ float pairsum(ull v) {
    float x, y;
    asm("mov.b64 {%0, %1}, %2;" : "=f"(x), "=f"(y) : "l"(v));
    return x + y;
}
__device__ __forceinline__ float sigf(float x)  { return __fdividef(1.f, 1.f + __expf(-x)); }
__device__ __forceinline__ float tanhf_(float x){ return 1.f - __fdividef(2.f, 1.f + __expf(2.f * x)); }

__device__ __forceinline__ void cluster_sync() {
    asm volatile("barrier.cluster.arrive.aligned;" ::: "memory");
    asm volatile("barrier.cluster.wait.aligned;" ::: "memory");
}
__device__ __forceinline__ void mbar_init(uint32_t a, uint32_t cnt) {
    asm volatile("mbarrier.init.shared.b64 [%0], %1;" :: "r"(a), "r"(cnt) : "memory");
}
__device__ __forceinline__ void mbar_arrive_expect(uint32_t a, uint32_t tx) {
    asm volatile("mbarrier.arrive.expect_tx.shared.b64 _, [%0], %1;" :: "r"(a), "r"(tx) : "memory");
}
__device__ __forceinline__ void mbar_wait(uint32_t a, uint32_t par) {
    asm volatile(
        "{\n\t"
        ".reg .pred P;\n\t"
        "W%=:\n\t"
        "mbarrier.try_wait.parity.acquire.cluster.shared::cta.b64 P, [%0], %1, 0x989680;\n\t"
        "@P bra D%=;\n\t"
        "bra W%=;\n\t"
        "D%=:\n\t"
        "}"
        :: "r"(a), "r"(par) : "memory");
}
__device__ __forceinline__ void s2s_bulk(uint32_t dst, uint32_t src, uint32_t bytes, uint32_t rmbar) {
    asm volatile("cp.async.bulk.shared::cluster.shared::cta.mbarrier::complete_tx::bytes [%0], [%1], %2, [%3];"
                 :: "r"(dst), "r"(src), "r"(bytes), "r"(rmbar) : "memory");
}

__device__ __forceinline__ unsigned short bfb(float x) {
    __nv_bfloat16 h = __float2bfloat16(x);
    return reinterpret_cast<unsigned short&>(h);
}
__device__ __forceinline__ float bff(unsigned short u) {
    __nv_bfloat16 h = reinterpret_cast<unsigned short&>(u) ? reinterpret_cast<__nv_bfloat16&>(u) : reinterpret_cast<__nv_bfloat16&>(u);
    return __bfloat162float(h);
}
// pack float pair -> bf16 hi word + lo (residual) word
__device__ __forceinline__ void packhl(float x, float y, uint32_t& hi, uint32_t& lo) {
    unsigned short h0 = bfb(x), h1 = bfb(y);
    float r0 = x - bff(h0), r1 = y - bff(h1);
    hi = (uint32_t)h0 | ((uint32_t)h1 << 16);
    lo = (uint32_t)bfb(r0) | ((uint32_t)bfb(r1) << 16);
}

// HMMA m16n8k16 bf16 -> f32 (portable, sm_80+; compiles on baseline sm_100)
__device__ __forceinline__ void mma16816(float* d, const uint32_t* a, uint32_t b0, uint32_t b1) {
    asm("mma.sync.aligned.m16n8k16.row.col.f32.bf16.bf16.f32 "
        "{%0,%1,%2,%3}, {%4,%5,%6,%7}, {%8,%9}, {%0,%1,%2,%3};"
        : "+f"(d[0]), "+f"(d[1]), "+f"(d[2]), "+f"(d[3])
        : "r"(a[0]), "r"(a[1]), "r"(a[2]), "r"(a[3]), "r"(b0), "r"(b1));
}

// ---------------- K1a: per-vocab duration table ----------------
__global__ void k_durtab(const float* __restrict__ embed, const float* __restrict__ dpw,
                         const float* __restrict__ dpb) {
    __shared__ float w[EMB_];
    int t = threadIdx.x;
    if (t < EMB_) w[t] = dpw[t];
    __syncthreads();
    const float* e = embed + t * EMB_;
    double acc = (double)dpb[0];
#pragma unroll 8
    for (int k = 0; k < EMB_; k++) acc += (double)e[k] * (double)w[k];
    float d = (float)acc;
    if (d < 0.f) d = 0.f;
    g_durTab[t] = (int)floorf(d) + 1;
}

// ---------------- K1b: per-batch scan + token scatter ----------------
__global__ void k_expand(const int* __restrict__ x) {
    __shared__ int s[T_];
    int b = blockIdx.x, t = threadIdx.x;
    int tokid = x[b * T_ + t];
    s[t] = g_durTab[tokid];
    __syncthreads();
    for (int off = 1; off < T_; off <<= 1) {
        int v = s[t];
        int a = (t >= off) ? s[t - off] : 0;
        __syncthreads();
        s[t] = v + a;
        __syncthreads();
    }
    for (int p = t; p < LMAX_; p += T_) g_tok[b * LMAX_ + p] = 256;
    __syncthreads();
    int st = t ? s[t - 1] : 0;
    int en = s[t];
    if (en > LMAX_) en = LMAX_;
    for (int p = st; p < en; p++) g_tok[b * LMAX_ + p] = tokid;
}

// ---------------- K2: per-vocab input-projection tables ----------------
__global__ void __launch_bounds__(256, 1)
k_proj(const float* __restrict__ embed,
       const float* __restrict__ wih_f, const float* __restrict__ bih_f, const float* __restrict__ bhh_f,
       const float* __restrict__ wih_b, const float* __restrict__ bih_b, const float* __restrict__ bhh_b) {
    extern __shared__ float se[];
    int dir = blockIdx.y;
    const float* wih = dir ? wih_b : wih_f;
    const float* bi  = dir ? bih_b : bih_f;
    const float* bh  = dir ? bhh_b : bhh_f;
    int tid = threadIdx.x;
    for (int i = tid; i < 257 * 128; i += 256)
        se[i] = (i < 256 * 128) ? embed[i] : 0.f;
    __syncthreads();

    int rloc = tid >> 1, hf = tid & 1;
    int r = blockIdx.x * 128 + rloc;
    ull wreg[32];
    const ulonglong2* wp = (const ulonglong2*)(wih + r * EMB_ + hf * 64);
#pragma unroll
    for (int i = 0; i < 16; i++) { ulonglong2 u = wp[i]; wreg[2 * i] = u.x; wreg[2 * i + 1] = u.y; }
    float bsum = bi[r] + bh[r];

    for (int v = 0; v < 257; v++) {
        const float* ev = se + v * 128 + hf * 64;
        ull acc = 0ull;
#pragma unroll
        for (int i = 0; i < 16; i++) {
            ulonglong2 e2 = *(const ulonglong2*)(ev + i * 4);
            acc = fma2(wreg[2 * i], e2.x, acc);
            acc = fma2(wreg[2 * i + 1], e2.y, acc);
        }
        float part = pairsum(acc);
        float other = __shfl_xor_sync(0xFFFFFFFFu, part, 1);
        if (hf == 0)
            g_projE[(dir * 257 + v) * 1024 + r] = part + other + bsum;
    }
}

// ---------------- K3: persistent cluster biLSTM on HMMA (mma.sync bf16 hi/lo) ----------------
// 8 clusters x 8 CTAs x 512 thr. cluster = (dir, 16-batch group). CTA rank owns hidden slice
// [32k, 32k+32) = 128 gate rows. Warp (mt = w&7, kh = w>>3): rows mt*16..+15, K-half kh.
// A fragments (Whh bf16 hi/lo) live in regs (64/thread), loaded once. Per step: h(fp32,16x256) ->
// B fragments (per-lane layout in smem) -> 48 HMMA/warp (3 products) -> scr -> gates -> exchange.
// smem byte offsets
#define HB_OF  0            // hbuf  [2][rank 8][b 16][32] fp32   (32768 B)
#define STG_OF 32768        // stg   [2][b 16][32] fp32           (4096 B)
#define SCR_OF 36864        // scr   [kh 2][m 128][17] fp32       (17408 B)
#define FBH_OF 54272        // B frags hi [ktg 16][nt 2][lane 32][2] u32 (8192 B)
#define FBL_OF 62464        // B frags lo                          (8192 B)
#define MB_OF  70656        // 2 mbarriers
#define SMEM_LSTM 70720

__global__ void __cluster_dims__(8, 1, 1) __launch_bounds__(512, 1)
k_lstm(const float* __restrict__ whh_f, const float* __restrict__ whh_b, int L) {
    extern __shared__ __align__(1024) char sm[];
    float*    hbuf = (float*)(sm + HB_OF);
    float*    stg  = (float*)(sm + STG_OF);
    float*    scr  = (float*)(sm + SCR_OF);
    uint32_t* fbh  = (uint32_t*)(sm + FBH_OF);
    uint32_t* fbl  = (uint32_t*)(sm + FBL_OF);

    int tid = threadIdx.x;
    int w = tid >> 5, lane = tid & 31;
    int gid = lane >> 2, tig = lane & 3;
    int bx = blockIdx.x;
    int rank = bx & 7;
    int cid = bx >> 3;
    int dir = cid >> 2;
    int quad = cid & 3;
    const float* whh = dir ? whh_b : whh_f;

    uint32_t hb_s = (uint32_t)__cvta_generic_to_shared(sm) + HB_OF;
    uint32_t st_s = (uint32_t)__cvta_generic_to_shared(sm) + STG_OF;
    uint32_t mb_s = (uint32_t)__cvta_generic_to_shared(sm) + MB_OF;

    // ---- load Whh slice -> A fragments (bf16 hi/lo) in registers, once ----
    int mt = w & 7, kh = w >> 3;
    uint32_t ahi[8][4], alo[8][4];
    {
        int m0 = mt * 16 + gid, m1 = m0 + 8;
        int g0 = (m0 >> 5) * 256 + rank * 32 + (m0 & 31);
        int g1 = (m1 >> 5) * 256 + rank * 32 + (m1 & 31);
        const float* r0 = whh + g0 * 256 + kh * 128;
        const float* r1 = whh + g1 * 256 + kh * 128;
#pragma unroll
        for (int kt = 0; kt < 8; kt++) {
            int c0 = kt * 16 + tig * 2;
            float2 v;
            v = *(const float2*)(r0 + c0);     packhl(v.x, v.y, ahi[kt][0], alo[kt][0]);
            v = *(const float2*)(r1 + c0);     packhl(v.x, v.y, ahi[kt][1], alo[kt][1]);
            v = *(const float2*)(r0 + c0 + 8); packhl(v.x, v.y, ahi[kt][2], alo[kt][2]);
            v = *(const float2*)(r1 + c0 + 8); packhl(v.x, v.y, ahi[kt][3], alo[kt][3]);
        }
    }

    for (int i = tid; i < 8192; i += 512) hbuf[i] = 0.f;   // both phases zero

    if (tid == 0) {
        mbar_init(mb_s, 1);
        mbar_init(mb_s + 8, 1);
        asm volatile("fence.mbarrier_init.release.cluster;" ::: "memory");
        mbar_arrive_expect(mb_s, 16384);       // pre-arm both h phases (8 x 2KB)
        mbar_arrive_expect(mb_s + 8, 16384);
    }
    __syncthreads();
    cluster_sync();

    // stage-2 identity: batch b2 = warp, hidden j2 = lane (512 threads = 16 x 32)
    int b2 = w, j2 = lane;
    int bg = quad * 16 + b2;
    float c = 0.f;
    unsigned par0 = 0, par1 = 0;
    int p = 0;

    for (int s = 0; s < L; s++) {
        int pos = dir ? (L - 1 - s) : s;
        // early gathers for stage 2
        int tok = g_tok[bg * LMAX_ + pos];
        const float* pe = g_projE + (dir * 257 + tok) * 1024 + rank * 32 + j2;
        float p_i = pe[0], p_f = pe[256], p_g = pe[512], p_o = pe[768];

        if (s > 0) {
            uint32_t mb = mb_s + (uint32_t)(p * 8);
            unsigned par = p ? par1 : par0;
            mbar_wait(mb, par);
            if (p) par1 ^= 1; else par0 ^= 1;
            if (tid == 0) mbar_arrive_expect(mb, 16384);   // rearm 2 steps ahead
        }

        // ---- convert h (fp32) -> B fragments (bf16 hi/lo, exact per-lane layout) ----
        {
            int n = tid & 15;
            int kp0 = tid >> 4;                 // 32 kpair groups
#pragma unroll
            for (int it = 0; it < 4; it++) {
                int kpair = kp0 + it * 32;      // k = kpair*2
                const float* hs = hbuf + p * 4096 + (kpair >> 4) * 512 + n * 32 + (kpair & 15) * 2;
                float2 hv = *(const float2*)hs;
                uint32_t whi, wlo;
                packhl(hv.x, hv.y, whi, wlo);
                int kt = kpair >> 3, reg = (kpair >> 2) & 1, tg = kpair & 3;
                int nt = n >> 3, gd = n & 7;
                int widx = ((kt * 2 + nt) * 32 + gd * 4 + tg) * 2 + reg;
                fbh[widx] = whi;
                fbl[widx] = wlo;
            }
        }
        __syncthreads();

        // ---- HMMA: D[128x16] = Whh_slice . h  (3 products: hihi + hilo + lohi) ----
        {
            float d[2][4] = {{0.f, 0.f, 0.f, 0.f}, {0.f, 0.f, 0.f, 0.f}};
#pragma unroll
            for (int kt = 0; kt < 8; kt++) {
                int ktg = kh * 8 + kt;
#pragma unroll
                for (int nt = 0; nt < 2; nt++) {
                    uint2 bh = *(const uint2*)(fbh + ((ktg * 2 + nt) * 32 + lane) * 2);
                    uint2 bl = *(const uint2*)(fbl + ((ktg * 2 + nt) * 32 + lane) * 2);
                    mma16816(d[nt], ahi[kt], bh.x, bh.y);
                    mma16816(d[nt], ahi[kt], bl.x, bl.y);
                    mma16816(d[nt], alo[kt], bh.x, bh.y);
                }
            }
            float* sc = scr + kh * 2176;        // 128*17
            int m0 = mt * 16 + gid;
#pragma unroll
            for (int nt = 0; nt < 2; nt++) {
                int n0 = nt * 8 + tig * 2;
                sc[m0 * 17 + n0]           = d[nt][0];
                sc[m0 * 17 + n0 + 1]       = d[nt][1];
                sc[(m0 + 8) * 17 + n0]     = d[nt][2];
                sc[(m0 + 8) * 17 + n0 + 1] = d[nt][3];
            }
        }
        __syncthreads();

        // ---- stage 2: combine K-halves + gates, update c/h for (b2, j2) ----
        {
            const float* s0 = scr;
            const float* s1 = scr + 2176;
            float gi = p_i + s0[(      j2) * 17 + b2] + s1[(      j2) * 17 + b2];
            float gf = p_f + s0[( 32 + j2) * 17 + b2] + s1[( 32 + j2) * 17 + b2];
            float gg = p_g + s0[( 64 + j2) * 17 + b2] + s1[( 64 + j2) * 17 + b2];
            float go = p_o + s0[( 96 + j2) * 17 + b2] + s1[( 96 + j2) * 17 + b2];
            c = sigf(gf) * c + sigf(gi) * tanhf_(gg);
            float h = sigf(go) * tanhf_(c);

            g_hout[(((size_t)dir * 64 + bg) * L + pos) * 256 + rank * 32 + j2] = h;
            if (s + 1 < L) stg[p * 512 + b2 * 32 + j2] = h;
        }
        __syncthreads();
        if (s + 1 < L && tid < 8) {
            asm volatile("fence.proxy.async.shared::cta;" ::: "memory");
            uint32_t dst = hb_s + (uint32_t)((p ^ 1) * 16384 + rank * 2048);
            uint32_t mb  = mb_s + (uint32_t)((p ^ 1) * 8);
            uint32_t src = st_s + (uint32_t)(p * 2048);
            uint32_t ra, rm;
            asm volatile("mapa.shared::cluster.u32 %0, %1, %2;" : "=r"(ra) : "r"(dst), "r"(tid));
            asm volatile("mapa.shared::cluster.u32 %0, %1, %2;" : "=r"(rm) : "r"(mb), "r"(tid));
            s2s_bulk(ra, src, 2048, rm);
        }
        p ^= 1;
    }
    cluster_sync();                            // exit safety
}

// ---------------- K4: final linear (B*L, 512) @ (512, 80) + bias ----------------
#define SW 514
#define ROWS_LIN 24
__global__ void __launch_bounds__(192, 1)
k_lin(const float* __restrict__ linw, const float* __restrict__ linb,
      float* __restrict__ out, int L, int R) {
    extern __shared__ float smf[];
    float* sw = smf;
    float* sh = smf + 80 * SW;
    int tid = threadIdx.x;
    int r0g = blockIdx.x * ROWS_LIN;

    for (int i = tid; i < 80 * 256; i += 192) {
        int m = i >> 8, k = (i & 255) * 2;
        float2 v = *(const float2*)(linw + m * 512 + k);
        *(float2*)(sw + m * SW + k) = v;
    }
    for (int i = tid; i < ROWS_LIN * 128; i += 192) {
        int rl = i >> 7, k = (i & 127) * 4;
        int rg = r0g + rl;
        float4 v = make_float4(0.f, 0.f, 0.f, 0.f);
        if (rg < R) {
            int b = rg / L, pos = rg % L;
            int d = k >> 8, j = k & 255;
            v = *(const float4*)(g_hout + (((size_t)d * 64 + b) * L + pos) * 256 + j);
        }
        *(float2*)(sh + rl * SW + k)     = make_float2(v.x, v.y);
        *(float2*)(sh + rl * SW + k + 2) = make_float2(v.z, v.w);
    }
    __syncthreads();

    int mg = tid & 15, rp = tid >> 4;
    int ra = rp * 2, rb = rp * 2 + 1;
    ull a0[5], a1[5];
#pragma unroll
    for (int i = 0; i < 5; i++) { a0[i] = 0ull; a1[i] = 0ull; }
#pragma unroll 8
    for (int kp = 0; kp < 256; kp++) {
        int k = kp * 2;
        ull h0 = *(const ull*)(sh + ra * SW + k);
        ull h1 = *(const ull*)(sh + rb * SW + k);
#pragma unroll
        for (int i = 0; i < 5; i++) {
            ull wv = *(const ull*)(sw + (mg + 16 * i) * SW + k);
            a0[i] = fma2(wv, h0, a0[i]);
            a1[i] = fma2(wv, h1, a1[i]);
        }
    }
#pragma unroll
    for (int i = 0; i < 5; i++) {
        int m = mg + 16 * i;
        float bm = linb[m];
        int rga = r0g + ra, rgb = r0g + rb;
        if (rga < R) out[(size_t)rga * MEL_ + m] = pairsum(a0[i]) + bm;
        if (rgb < R) out[(size_t)rgb * MEL_ + m] = pairsum(a1[i]) + bm;
    }
}

// ---------------- launch ----------------
extern "C" void kernel_launch(void* const* d_in, const int* in_sizes, int n_in,
                              void* d_out, int out_size) {
    const int*   x     = (const int*)  d_in[0];
    const float* embed = (const float*)d_in[1];
    const float* dpw   = (const float*)d_in[2];
    const float* dpb   = (const float*)d_in[3];
    const float* wihf  = (const float*)d_in[4];
    const float* whhf  = (const float*)d_in[5];
    const float* bihf  = (const float*)d_in[6];
    const float* bhhf  = (const float*)d_in[7];
    const float* wihb  = (const float*)d_in[8];
    const float* whhb  = (const float*)d_in[9];
    const float* bihb  = (const float*)d_in[10];
    const float* bhhb  = (const float*)d_in[11];
    const float* linw  = (const float*)d_in[12];
    const float* linb  = (const float*)d_in[13];
    float* out = (float*)d_out;

    int L = out_size / (B_ * MEL_);
    if (L > LMAX_) L = LMAX_;
    int R = B_ * L;

    k_durtab<<<1, 256>>>(embed, dpw, dpb);
    k_expand<<<B_, T_>>>(x);

    int smem_proj = 257 * 128 * 4;
    cudaFuncSetAttribute(k_proj, cudaFuncAttributeMaxDynamicSharedMemorySize, smem_proj);
    k_proj<<<dim3(8, 2, 1), 256, smem_proj>>>(embed, wihf, bihf, bhhf, wihb, bihb, bhhb);

    cudaFuncSetAttribute(k_lstm, cudaFuncAttributeMaxDynamicSharedMemorySize, SMEM_LSTM);
    k_lstm<<<64, 512, SMEM_LSTM>>>(whhf, whhb, L);

    int smem_lin = 104 * SW * 4;
    cudaFuncSetAttribute(k_lin, cudaFuncAttributeMaxDynamicSharedMemorySize, smem_lin);
    k_lin<<<(R + ROWS_LIN - 1) / ROWS_LIN, 192, smem_lin>>>(linw, linb, out, L, R);
}

// round 9
// speedup vs baseline: 2.6687x; 1.4984x over previous
#include <cuda_runtime.h>
#include <cuda_bf16.h>
#include <cstdint>
#include <cstdio>

#define B_ 64
#define T_ 512
#define EMB_ 128
#define HID_ 256
#define MEL_ 80
#define LMAX_ 2048

typedef unsigned long long ull;

// ---------------- static device scratch ----------------
__device__ int   g_durTab[256];
__device__ int   g_tok[B_ * LMAX_];                 // vocab id per expanded pos, 256 = pad
__device__ float g_projE[2 * 257 * 1024];           // Wih@embed[v] + bih + bhh  (entry 256 = bias only)
__device__ float g_hout[2ull * B_ * LMAX_ * HID_];  // [dir][b][pos][256]

// ---------------- generic helpers ----------------
__device__ __forceinline__ ull fma2(ull a, ull b, ull c) {
    ull d;
    asm("fma.rn.f32x2 %0, %1, %2, %3;" : "=l"(d) : "l"(a), "l"(b), "l"(c));
    return d;
}
__device__ __forceinline__ float pairsum(ull v) {
    float x, y;
    asm("mov.b64 {%0, %1}, %2;" : "=f"(x), "=f"(y) : "l"(v));
    return x + y;
}
__device__ __forceinline__ float sigf(float x)  { return __fdividef(1.f, 1.f + __expf(-x)); }
__device__ __forceinline__ float tanhf_(float x){ return 1.f - __fdividef(2.f, 1.f + __expf(2.f * x)); }

__device__ __forceinline__ void cluster_sync() {
    asm volatile("barrier.cluster.arrive.aligned;" ::: "memory");
    asm volatile("barrier.cluster.wait.aligned;" ::: "memory");
}
__device__ __forceinline__ void mbar_init(uint32_t a, uint32_t cnt) {
    asm volatile("mbarrier.init.shared.b64 [%0], %1;" :: "r"(a), "r"(cnt) : "memory");
}
__device__ __forceinline__ void mbar_arrive_expect(uint32_t a, uint32_t tx) {
    asm volatile("mbarrier.arrive.expect_tx.shared.b64 _, [%0], %1;" :: "r"(a), "r"(tx) : "memory");
}
__device__ __forceinline__ void mbar_wait(uint32_t a, uint32_t par) {
    asm volatile(
        "{\n\t"
        ".reg .pred P;\n\t"
        "W%=:\n\t"
        "mbarrier.try_wait.parity.acquire.cluster.shared::cta.b64 P, [%0], %1, 0x989680;\n\t"
        "@P bra D%=;\n\t"
        "bra W%=;\n\t"
        "D%=:\n\t"
        "}"
        :: "r"(a), "r"(par) : "memory");
}
__device__ __forceinline__ void s2s_bulk(uint32_t dst, uint32_t src, uint32_t bytes, uint32_t rmbar) {
    asm volatile("cp.async.bulk.shared::cluster.shared::cta.mbarrier::complete_tx::bytes [%0], [%1], %2, [%3];"
                 :: "r"(dst), "r"(src), "r"(bytes), "r"(rmbar) : "memory");
}

__device__ __forceinline__ unsigned short bfb(float x) {
    __nv_bfloat16 h = __float2bfloat16(x);
    return reinterpret_cast<unsigned short&>(h);
}
__device__ __forceinline__ float bff(unsigned short u) {
    __nv_bfloat16 h = reinterpret_cast<__nv_bfloat16&>(u);
    return __bfloat162float(h);
}
__device__ __forceinline__ void packhl(float x, float y, uint32_t& hi, uint32_t& lo) {
    unsigned short h0 = bfb(x), h1 = bfb(y);
    float r0 = x - bff(h0), r1 = y - bff(h1);
    hi = (uint32_t)h0 | ((uint32_t)h1 << 16);
    lo = (uint32_t)bfb(r0) | ((uint32_t)bfb(r1) << 16);
}

// HMMA m16n8k16 bf16 -> f32 (portable, sm_80+)
__device__ __forceinline__ void mma16816(float* d, const uint32_t* a, uint32_t b0, uint32_t b1) {
    asm("mma.sync.aligned.m16n8k16.row.col.f32.bf16.bf16.f32 "
        "{%0,%1,%2,%3}, {%4,%5,%6,%7}, {%8,%9}, {%0,%1,%2,%3};"
        : "+f"(d[0]), "+f"(d[1]), "+f"(d[2]), "+f"(d[3])
        : "r"(a[0]), "r"(a[1]), "r"(a[2]), "r"(a[3]), "r"(b0), "r"(b1));
}

// ---------------- K1a: per-vocab duration table ----------------
__global__ void k_durtab(const float* __restrict__ embed, const float* __restrict__ dpw,
                         const float* __restrict__ dpb) {
    __shared__ float w[EMB_];
    int t = threadIdx.x;
    if (t < EMB_) w[t] = dpw[t];
    __syncthreads();
    const float* e = embed + t * EMB_;
    double acc = (double)dpb[0];
#pragma unroll 8
    for (int k = 0; k < EMB_; k++) acc += (double)e[k] * (double)w[k];
    float d = (float)acc;
    if (d < 0.f) d = 0.f;
    g_durTab[t] = (int)floorf(d) + 1;
}

// ---------------- K1b: per-batch scan + token scatter ----------------
__global__ void k_expand(const int* __restrict__ x) {
    __shared__ int s[T_];
    int b = blockIdx.x, t = threadIdx.x;
    int tokid = x[b * T_ + t];
    s[t] = g_durTab[tokid];
    __syncthreads();
    for (int off = 1; off < T_; off <<= 1) {
        int v = s[t];
        int a = (t >= off) ? s[t - off] : 0;
        __syncthreads();
        s[t] = v + a;
        __syncthreads();
    }
    for (int p = t; p < LMAX_; p += T_) g_tok[b * LMAX_ + p] = 256;
    __syncthreads();
    int st = t ? s[t - 1] : 0;
    int en = s[t];
    if (en > LMAX_) en = LMAX_;
    for (int p = st; p < en; p++) g_tok[b * LMAX_ + p] = tokid;
}

// ---------------- K2: per-vocab input-projection tables ----------------
__global__ void __launch_bounds__(256, 1)
k_proj(const float* __restrict__ embed,
       const float* __restrict__ wih_f, const float* __restrict__ bih_f, const float* __restrict__ bhh_f,
       const float* __restrict__ wih_b, const float* __restrict__ bih_b, const float* __restrict__ bhh_b) {
    extern __shared__ float se[];
    int dir = blockIdx.y;
    const float* wih = dir ? wih_b : wih_f;
    const float* bi  = dir ? bih_b : bih_f;
    const float* bh  = dir ? bhh_b : bhh_f;
    int tid = threadIdx.x;
    for (int i = tid; i < 257 * 128; i += 256)
        se[i] = (i < 256 * 128) ? embed[i] : 0.f;
    __syncthreads();

    int rloc = tid >> 1, hf = tid & 1;
    int r = blockIdx.x * 128 + rloc;
    ull wreg[32];
    const ulonglong2* wp = (const ulonglong2*)(wih + r * EMB_ + hf * 64);
#pragma unroll
    for (int i = 0; i < 16; i++) { ulonglong2 u = wp[i]; wreg[2 * i] = u.x; wreg[2 * i + 1] = u.y; }
    float bsum = bi[r] + bh[r];

    for (int v = 0; v < 257; v++) {
        const float* ev = se + v * 128 + hf * 64;
        ull acc = 0ull;
#pragma unroll
        for (int i = 0; i < 16; i++) {
            ulonglong2 e2 = *(const ulonglong2*)(ev + i * 4);
            acc = fma2(wreg[2 * i], e2.x, acc);
            acc = fma2(wreg[2 * i + 1], e2.y, acc);
        }
        float part = pairsum(acc);
        float other = __shfl_xor_sync(0xFFFFFFFFu, part, 1);
        if (hf == 0)
            g_projE[(dir * 257 + v) * 1024 + r] = part + other + bsum;
    }
}

// ---------------- K3: persistent cluster biLSTM, HMMA, 2 interleaved groups ----------------
// 8 clusters x 8 CTAs x 512 thr. cluster cid: dir = cid>>2, quad = cid&3 -> 16 seqs = 2 groups x 8.
// CTA rank owns hidden [32k,32k+32) = 128 gate rows. Warp (mt=w&7, kh=w>>3), N=8 per group MMA.
// h is exchanged AS bf16 hi/lo B-fragments: stage2 packs + 2x STS.U16 into fragment layout,
// bulk copies deliver straight into peers' fb tiles. No fp32 h buffer, no convert stage.
// smem (bytes):
#define FB_OF  0            // fb [g2][p2][ktg16][hl2][lane32][reg2] u32 = 32768
#define STG_OF 32768        // stg[g2][p2][2ktg][2hl][32][2] u32 = 4096
#define SCR_OF 36864        // scr[g2][kh2][128][9] f32 = 36864
#define MB_OF  73728        // 4 mbarriers [g][p]
#define SMEM_LSTM 73792

__global__ void __cluster_dims__(8, 1, 1) __launch_bounds__(512, 1)
k_lstm(const float* __restrict__ whh_f, const float* __restrict__ whh_b, int L) {
    extern __shared__ __align__(1024) char sm[];
    uint32_t* fb  = (uint32_t*)(sm + FB_OF);
    float*    scr = (float*)(sm + SCR_OF);

    int tid = threadIdx.x;
    int w = tid >> 5, lane = tid & 31;
    int gid = lane >> 2, tig = lane & 3;
    int bx = blockIdx.x;
    int rank = bx & 7;
    int cid = bx >> 3;
    int dir = cid >> 2;
    int quad = cid & 3;
    const float* whh = dir ? whh_b : whh_f;

    uint32_t sm_s = (uint32_t)__cvta_generic_to_shared(sm);
    uint32_t fb_s = sm_s + FB_OF;
    uint32_t st_s = sm_s + STG_OF;
    uint32_t mb_s = sm_s + MB_OF;

    // ---- Whh slice -> A fragments (bf16 hi/lo) in registers, loaded once ----
    int mt = w & 7, kh = w >> 3;
    uint32_t ahi[8][4], alo[8][4];
    {
        int m0 = mt * 16 + gid, m1 = m0 + 8;
        int g0 = (m0 >> 5) * 256 + rank * 32 + (m0 & 31);
        int g1 = (m1 >> 5) * 256 + rank * 32 + (m1 & 31);
        const float* r0 = whh + g0 * 256 + kh * 128;
        const float* r1 = whh + g1 * 256 + kh * 128;
#pragma unroll
        for (int kt = 0; kt < 8; kt++) {
            int c0 = kt * 16 + tig * 2;
            float2 v;
            v = *(const float2*)(r0 + c0);     packhl(v.x, v.y, ahi[kt][0], alo[kt][0]);
            v = *(const float2*)(r1 + c0);     packhl(v.x, v.y, ahi[kt][1], alo[kt][1]);
            v = *(const float2*)(r0 + c0 + 8); packhl(v.x, v.y, ahi[kt][2], alo[kt][2]);
            v = *(const float2*)(r1 + c0 + 8); packhl(v.x, v.y, ahi[kt][3], alo[kt][3]);
        }
    }

    for (int i = tid; i < 8192; i += 512) fb[i] = 0u;    // h=0 in both groups/phases

    if (tid == 0) {
#pragma unroll
        for (int q = 0; q < 4; q++) mbar_init(mb_s + 8 * q, 1);
        asm volatile("fence.mbarrier_init.release.cluster;" ::: "memory");
#pragma unroll
        for (int q = 0; q < 4; q++) mbar_arrive_expect(mb_s + 8 * q, 8192);
    }
    __syncthreads();
    cluster_sync();

    bool s2t = tid < 256;                    // stage-2 threads: b2 = warp, j2 = lane
    int b2 = tid >> 5, j2 = tid & 31;
    float cst[2] = {0.f, 0.f};
    unsigned parr = 0;                       // parity bit per q = g*2+p
    int p = 0;

    for (int s = 0; s < L; s++) {
        int pos = dir ? (L - 1 - s) : s;
#pragma unroll
        for (int g = 0; g < 2; g++) {
            int bg = quad * 16 + g * 8 + b2;
            float p_i = 0.f, p_f = 0.f, p_g = 0.f, p_o = 0.f;
            if (s2t) {                       // early gathers, consumed after HMMA
                int tok = g_tok[bg * LMAX_ + pos];
                const float* pe = g_projE + (dir * 257 + tok) * 1024 + rank * 32 + j2;
                p_i = pe[0]; p_f = pe[256]; p_g = pe[512]; p_o = pe[768];
            }
            int q = g * 2 + p;
            if (s > 0) {
                mbar_wait(mb_s + 8 * q, (parr >> q) & 1);
                parr ^= 1u << q;
                if (tid == 0) mbar_arrive_expect(mb_s + 8 * q, 8192);   // rearm 2 steps ahead
            }

            // ---- HMMA: D[128x8] = Whh_slice . h_g  (3 products, 2 acc chains) ----
            {
                const uint32_t* fbg = fb + q * 2048;
                float a0[4] = {0.f, 0.f, 0.f, 0.f};
                float a1[4] = {0.f, 0.f, 0.f, 0.f};
#pragma unroll
                for (int kt = 0; kt < 8; kt++) {
                    const uint32_t* base = fbg + (kh * 8 + kt) * 128;
                    uint2 bh = *(const uint2*)(base + lane * 2);
                    uint2 bl = *(const uint2*)(base + 64 + lane * 2);
                    mma16816(a0, ahi[kt], bh.x, bh.y);
                    mma16816(a1, ahi[kt], bl.x, bl.y);
                    mma16816(a1, alo[kt], bh.x, bh.y);
                }
                float* sc = scr + (g * 2 + kh) * 1152;
                int m0 = mt * 16 + gid, n0 = tig * 2;
                sc[m0 * 9 + n0]           = a0[0] + a1[0];
                sc[m0 * 9 + n0 + 1]       = a0[1] + a1[1];
                sc[(m0 + 8) * 9 + n0]     = a0[2] + a1[2];
                sc[(m0 + 8) * 9 + n0 + 1] = a0[3] + a1[3];
            }
            __syncthreads();

            // ---- stage 2: gates + state update + fragment pack (warps 0-7) ----
            if (s2t) {
                const float* s0 = scr + (g * 2) * 1152;
                const float* s1 = scr + (g * 2 + 1) * 1152;
                float gi = p_i + s0[(      j2) * 9 + b2] + s1[(      j2) * 9 + b2];
                float gf = p_f + s0[( 32 + j2) * 9 + b2] + s1[( 32 + j2) * 9 + b2];
                float gg = p_g + s0[( 64 + j2) * 9 + b2] + s1[( 64 + j2) * 9 + b2];
                float go = p_o + s0[( 96 + j2) * 9 + b2] + s1[( 96 + j2) * 9 + b2];
                float c = sigf(gf) * cst[g] + sigf(gi) * tanhf_(gg);
                cst[g] = c;
                float h = sigf(go) * tanhf_(c);

                g_hout[(((size_t)dir * 64 + bg) * L + pos) * 256 + rank * 32 + j2] = h;

                if (s + 1 < L) {             // pack h -> bf16 hi/lo directly in fragment layout
                    unsigned short hh = bfb(h);
                    unsigned short lh = bfb(h - bff(hh));
                    int ktg_l = j2 >> 4, reg = (j2 >> 3) & 1, tg = (j2 >> 1) & 3, hw = j2 & 1;
                    uint32_t base16 = (uint32_t)(q * 256);
                    uint32_t ehi = ((ktg_l * 2 + 0) * 32 + b2 * 4 + tg) * 2 + reg;
                    uint32_t elo = ((ktg_l * 2 + 1) * 32 + b2 * 4 + tg) * 2 + reg;
                    asm volatile("st.shared.u16 [%0], %1;"
                                 :: "r"(st_s + (base16 + ehi) * 4 + hw * 2), "h"(hh) : "memory");
                    asm volatile("st.shared.u16 [%0], %1;"
                                 :: "r"(st_s + (base16 + elo) * 4 + hw * 2), "h"(lh) : "memory");
                }
            }
            __syncthreads();
            if (s + 1 < L && tid < 8) {      // 8 x 1KB fragment copies to peers
                asm volatile("fence.proxy.async.shared::cta;" ::: "memory");
                uint32_t dst = fb_s + (uint32_t)(((g * 2 + (p ^ 1)) * 2048 + rank * 256) * 4);
                uint32_t mb  = mb_s + (uint32_t)((g * 2 + (p ^ 1)) * 8);
                uint32_t src = st_s + (uint32_t)(q * 1024);
                uint32_t ra, rm;
                asm volatile("mapa.shared::cluster.u32 %0, %1, %2;" : "=r"(ra) : "r"(dst), "r"(tid));
                asm volatile("mapa.shared::cluster.u32 %0, %1, %2;" : "=r"(rm) : "r"(mb), "r"(tid));
                s2s_bulk(ra, src, 1024, rm);
            }
        }
        p ^= 1;
    }
    cluster_sync();                          // exit safety
}

// ---------------- K4: final linear (B*L, 512) @ (512, 80) + bias ----------------
#define SW 514
#define ROWS_LIN 24
__global__ void __launch_bounds__(192, 1)
k_lin(const float* __restrict__ linw, const float* __restrict__ linb,
      float* __restrict__ out, int L, int R) {
    extern __shared__ float smf[];
    float* sw = smf;
    float* sh = smf + 80 * SW;
    int tid = threadIdx.x;
    int r0g = blockIdx.x * ROWS_LIN;

    for (int i = tid; i < 80 * 256; i += 192) {
        int m = i >> 8, k = (i & 255) * 2;
        float2 v = *(const float2*)(linw + m * 512 + k);
        *(float2*)(sw + m * SW + k) = v;
    }
    for (int i = tid; i < ROWS_LIN * 128; i += 192) {
        int rl = i >> 7, k = (i & 127) * 4;
        int rg = r0g + rl;
        float4 v = make_float4(0.f, 0.f, 0.f, 0.f);
        if (rg < R) {
            int b = rg / L, pos = rg % L;
            int d = k >> 8, j = k & 255;
            v = *(const float4*)(g_hout + (((size_t)d * 64 + b) * L + pos) * 256 + j);
        }
        *(float2*)(sh + rl * SW + k)     = make_float2(v.x, v.y);
        *(float2*)(sh + rl * SW + k + 2) = make_float2(v.z, v.w);
    }
    __syncthreads();

    int mg = tid & 15, rp = tid >> 4;
    int ra = rp * 2, rb = rp * 2 + 1;
    ull a0[5], a1[5];
#pragma unroll
    for (int i = 0; i < 5; i++) { a0[i] = 0ull; a1[i] = 0ull; }
#pragma unroll 8
    for (int kp = 0; kp < 256; kp++) {
        int k = kp * 2;
        ull h0 = *(const ull*)(sh + ra * SW + k);
        ull h1 = *(const ull*)(sh + rb * SW + k);
#pragma unroll
        for (int i = 0; i < 5; i++) {
            ull wv = *(const ull*)(sw + (mg + 16 * i) * SW + k);
            a0[i] = fma2(wv, h0, a0[i]);
            a1[i] = fma2(wv, h1, a1[i]);
        }
    }
#pragma unroll
    for (int i = 0; i < 5; i++) {
        int m = mg + 16 * i;
        float bm = linb[m];
        int rga = r0g + ra, rgb = r0g + rb;
        if (rga < R) out[(size_t)rga * MEL_ + m] = pairsum(a0[i]) + bm;
        if (rgb < R) out[(size_t)rgb * MEL_ + m] = pairsum(a1[i]) + bm;
    }
}

// ---------------- launch ----------------
extern "C" void kernel_launch(void* const* d_in, const int* in_sizes, int n_in,
                              void* d_out, int out_size) {
    const int*   x     = (const int*)  d_in[0];
    const float* embed = (const float*)d_in[1];
    const float* dpw   = (const float*)d_in[2];
    const float* dpb   = (const float*)d_in[3];
    const float* wihf  = (const float*)d_in[4];
    const float* whhf  = (const float*)d_in[5];
    const float* bihf  = (const float*)d_in[6];
    const float* bhhf  = (const float*)d_in[7];
    const float* wihb  = (const float*)d_in[8];
    const float* whhb  = (const float*)d_in[9];
    const float* bihb  = (const float*)d_in[10];
    const float* bhhb  = (const float*)d_in[11];
    const float* linw  = (const float*)d_in[12];
    const float* linb  = (const float*)d_in[13];
    float* out = (float*)d_out;

    int L = out_size / (B_ * MEL_);
    if (L > LMAX_) L = LMAX_;
    int R = B_ * L;

    k_durtab<<<1, 256>>>(embed, dpw, dpb);
    k_expand<<<B_, T_>>>(x);

    int smem_proj = 257 * 128 * 4;
    cudaFuncSetAttribute(k_proj, cudaFuncAttributeMaxDynamicSharedMemorySize, smem_proj);
    k_proj<<<dim3(8, 2, 1), 256, smem_proj>>>(embed, wihf, bihf, bhhf, wihb, bihb, bhhb);

    cudaFuncSetAttribute(k_lstm, cudaFuncAttributeMaxDynamicSharedMemorySize, SMEM_LSTM);
    k_lstm<<<64, 512, SMEM_LSTM>>>(whhf, whhb, L);

    int smem_lin = 104 * SW * 4;
    cudaFuncSetAttribute(k_lin, cudaFuncAttributeMaxDynamicSharedMemorySize, smem_lin);
    k_lin<<<(R + ROWS_LIN - 1) / ROWS_LIN, 192, smem_lin>>>(linw, linb, out, L, R);
}

// round 11
// speedup vs baseline: 2.9723x; 1.1137x over previous
#include <cuda_runtime.h>
#include <cuda_bf16.h>
#include <cstdint>
#include <cstdio>

#define B_ 64
#define T_ 512
#define EMB_ 128
#define HID_ 256
#define MEL_ 80
#define LMAX_ 2048

typedef unsigned long long ull;

// ---------------- static device scratch ----------------
__device__ int   g_durTab[256];
__device__ int   g_tok[B_ * LMAX_];                 // vocab id per expanded pos, 256 = pad
__device__ float g_projE[2 * 257 * 1024];           // Wih@embed[v] + bih + bhh  (entry 256 = bias only)
__device__ float g_hout[2ull * B_ * LMAX_ * HID_];  // [dir][b][pos][256]
__device__ uint4 g_linwF[320 * 32];                 // linw as B-frags: [kt*10+nt][lane]{hi0,hi1,lo0,lo1}

// ---------------- generic helpers ----------------
__device__ __forceinline__ ull fma2(ull a, ull b, ull c) {
    ull d;
    asm("fma.rn.f32x2 %0, %1, %2, %3;" : "=l"(d) : "l"(a), "l"(b), "l"(c));
    return d;
}
__device__ __forceinline__ float pairsum(ull v) {
    float x, y;
    asm("mov.b64 {%0, %1}, %2;" : "=f"(x), "=f"(y) : "l"(v));
    return x + y;
}
__device__ __forceinline__ float sigf(float x)  { return __fdividef(1.f, 1.f + __expf(-x)); }
__device__ __forceinline__ float tanhf_(float x){ return 1.f - __fdividef(2.f, 1.f + __expf(2.f * x)); }

__device__ __forceinline__ void cluster_sync() {
    asm volatile("barrier.cluster.arrive.aligned;" ::: "memory");
    asm volatile("barrier.cluster.wait.aligned;" ::: "memory");
}
__device__ __forceinline__ void mbar_init(uint32_t a, uint32_t cnt) {
    asm volatile("mbarrier.init.shared.b64 [%0], %1;" :: "r"(a), "r"(cnt) : "memory");
}
__device__ __forceinline__ void mbar_arrive_expect(uint32_t a, uint32_t tx) {
    asm volatile("mbarrier.arrive.expect_tx.shared.b64 _, [%0], %1;" :: "r"(a), "r"(tx) : "memory");
}
__device__ __forceinline__ void mbar_wait(uint32_t a, uint32_t par) {
    asm volatile(
        "{\n\t"
        ".reg .pred P;\n\t"
        "W%=:\n\t"
        "mbarrier.try_wait.parity.acquire.cluster.shared::cta.b64 P, [%0], %1, 0x989680;\n\t"
        "@P bra D%=;\n\t"
        "bra W%=;\n\t"
        "D%=:\n\t"
        "}"
        :: "r"(a), "r"(par) : "memory");
}
__device__ __forceinline__ void s2s_bulk(uint32_t dst, uint32_t src, uint32_t bytes, uint32_t rmbar) {
    asm volatile("cp.async.bulk.shared::cluster.shared::cta.mbarrier::complete_tx::bytes [%0], [%1], %2, [%3];"
                 :: "r"(dst), "r"(src), "r"(bytes), "r"(rmbar) : "memory");
}

__device__ __forceinline__ unsigned short bfb(float x) {
    __nv_bfloat16 h = __float2bfloat16(x);
    return reinterpret_cast<unsigned short&>(h);
}
__device__ __forceinline__ float bff(unsigned short u) {
    __nv_bfloat16 h = reinterpret_cast<__nv_bfloat16&>(u);
    return __bfloat162float(h);
}
__device__ __forceinline__ void packhl(float x, float y, uint32_t& hi, uint32_t& lo) {
    unsigned short h0 = bfb(x), h1 = bfb(y);
    float r0 = x - bff(h0), r1 = y - bff(h1);
    hi = (uint32_t)h0 | ((uint32_t)h1 << 16);
    lo = (uint32_t)bfb(r0) | ((uint32_t)bfb(r1) << 16);
}

// HMMA m16n8k16 bf16 -> f32 (portable, sm_80+)
__device__ __forceinline__ void mma16816(float* d, const uint32_t* a, uint32_t b0, uint32_t b1) {
    asm("mma.sync.aligned.m16n8k16.row.col.f32.bf16.bf16.f32 "
        "{%0,%1,%2,%3}, {%4,%5,%6,%7}, {%8,%9}, {%0,%1,%2,%3};"
        : "+f"(d[0]), "+f"(d[1]), "+f"(d[2]), "+f"(d[3])
        : "r"(a[0]), "r"(a[1]), "r"(a[2]), "r"(a[3]), "r"(b0), "r"(b1));
}

// ---------------- K1a: per-vocab duration table ----------------
__global__ void k_durtab(const float* __restrict__ embed, const float* __restrict__ dpw,
                         const float* __restrict__ dpb) {
    __shared__ float w[EMB_];
    int t = threadIdx.x;
    if (t < EMB_) w[t] = dpw[t];
    __syncthreads();
    const float* e = embed + t * EMB_;
    double acc = (double)dpb[0];
#pragma unroll 8
    for (int k = 0; k < EMB_; k++) acc += (double)e[k] * (double)w[k];
    float d = (float)acc;
    if (d < 0.f) d = 0.f;
    g_durTab[t] = (int)floorf(d) + 1;
}

// ---------------- K1b: per-batch scan + token scatter ----------------
__global__ void k_expand(const int* __restrict__ x) {
    __shared__ int s[T_];
    int b = blockIdx.x, t = threadIdx.x;
    int tokid = x[b * T_ + t];
    s[t] = g_durTab[tokid];
    __syncthreads();
    for (int off = 1; off < T_; off <<= 1) {
        int v = s[t];
        int a = (t >= off) ? s[t - off] : 0;
        __syncthreads();
        s[t] = v + a;
        __syncthreads();
    }
    for (int p = t; p < LMAX_; p += T_) g_tok[b * LMAX_ + p] = 256;
    __syncthreads();
    int st = t ? s[t - 1] : 0;
    int en = s[t];
    if (en > LMAX_) en = LMAX_;
    for (int p = st; p < en; p++) g_tok[b * LMAX_ + p] = tokid;
}

// ---------------- K2: per-vocab input-projection tables (v-chunked, grid x4) ----------------
__global__ void __launch_bounds__(256, 1)
k_proj(const float* __restrict__ embed,
       const float* __restrict__ wih_f, const float* __restrict__ bih_f, const float* __restrict__ bhh_f,
       const float* __restrict__ wih_b, const float* __restrict__ bih_b, const float* __restrict__ bhh_b) {
    extern __shared__ float se[];               // [<=65][128]
    int dir = blockIdx.y;
    int chunk = blockIdx.z;
    int v0 = chunk * 65;
    int cnt = 257 - v0; if (cnt > 65) cnt = 65;
    const float* wih = dir ? wih_b : wih_f;
    const float* bi  = dir ? bih_b : bih_f;
    const float* bh  = dir ? bhh_b : bhh_f;
    int tid = threadIdx.x;
    for (int i = tid; i < cnt * 128; i += 256) {
        int v = v0 + (i >> 7);
        se[i] = (v < 256) ? embed[v * 128 + (i & 127)] : 0.f;
    }
    __syncthreads();

    int rloc = tid >> 1, hf = tid & 1;
    int r = blockIdx.x * 128 + rloc;
    ull wreg[32];
    const ulonglong2* wp = (const ulonglong2*)(wih + r * EMB_ + hf * 64);
#pragma unroll
    for (int i = 0; i < 16; i++) { ulonglong2 u = wp[i]; wreg[2 * i] = u.x; wreg[2 * i + 1] = u.y; }
    float bsum = bi[r] + bh[r];

    for (int vv = 0; vv < cnt; vv++) {
        const float* ev = se + vv * 128 + hf * 64;
        ull acc = 0ull;
#pragma unroll
        for (int i = 0; i < 16; i++) {
            ulonglong2 e2 = *(const ulonglong2*)(ev + i * 4);
            acc = fma2(wreg[2 * i], e2.x, acc);
            acc = fma2(wreg[2 * i + 1], e2.y, acc);
        }
        float part = pairsum(acc);
        float other = __shfl_xor_sync(0xFFFFFFFFu, part, 1);
        if (hf == 0)
            g_projE[(dir * 257 + v0 + vv) * 1024 + r] = part + other + bsum;
    }
}

// ---------------- K2b: pack linw into HMMA B-fragments (once) ----------------
__global__ void k_linprep(const float* __restrict__ linw) {
    int ww = blockIdx.x * 8 + (threadIdx.x >> 5);   // 0..319 = kt*10+nt
    int lane = threadIdx.x & 31;
    int nt = ww % 10, kt = ww / 10;
    int gid = lane >> 2, tig = lane & 3;
    int n = nt * 8 + gid;
    int k0 = kt * 16 + tig * 2;
    const float* p = linw + n * 512;
    uint32_t h0, l0, h1, l1;
    packhl(p[k0], p[k0 + 1], h0, l0);
    packhl(p[k0 + 8], p[k0 + 9], h1, l1);
    g_linwF[ww * 32 + lane] = make_uint4(h0, h1, l0, l1);
}

// ---------------- K3: persistent cluster biLSTM, HMMA, 2 interleaved groups ----------------
// Producer warps (8-15) use bar.arrive on PER-GROUP barrier ids (1+g) and run ahead.
// (Single shared id deadlocks: producers arrive twice per step -> spurious self-release.)
// smem (bytes):
#define FB_OF  0            // fb [g2][p2][ktg16][hl2][lane32][reg2] u32 = 32768
#define STG_OF 32768        // stg[g2][p2][256] u32 = 4096
#define SCR_OF 36864        // scr[g2][kh2][128][9] f32 = 36864
#define MB_OF  73728        // 4 mbarriers [g][p]
#define SMEM_LSTM 73792

__global__ void __cluster_dims__(8, 1, 1) __launch_bounds__(512, 1)
k_lstm(const float* __restrict__ whh_f, const float* __restrict__ whh_b, int L) {
    extern __shared__ __align__(1024) char sm[];
    uint32_t* fb  = (uint32_t*)(sm + FB_OF);
    float*    scr = (float*)(sm + SCR_OF);

    int tid = threadIdx.x;
    int w = tid >> 5, lane = tid & 31;
    int gid = lane >> 2, tig = lane & 3;
    int bx = blockIdx.x;
    int rank = bx & 7;
    int cid = bx >> 3;
    int dir = cid >> 2;
    int quad = cid & 3;
    const float* whh = dir ? whh_b : whh_f;

    uint32_t sm_s = (uint32_t)__cvta_generic_to_shared(sm);
    uint32_t fb_s = sm_s + FB_OF;
    uint32_t st_s = sm_s + STG_OF;
    uint32_t mb_s = sm_s + MB_OF;

    // ---- Whh slice -> A fragments (bf16 hi/lo) in registers, loaded once ----
    int mt = w & 7, kh = w >> 3;
    uint32_t ahi[8][4], alo[8][4];
    {
        int m0 = mt * 16 + gid, m1 = m0 + 8;
        int g0 = (m0 >> 5) * 256 + rank * 32 + (m0 & 31);
        int g1 = (m1 >> 5) * 256 + rank * 32 + (m1 & 31);
        const float* r0 = whh + g0 * 256 + kh * 128;
        const float* r1 = whh + g1 * 256 + kh * 128;
#pragma unroll
        for (int kt = 0; kt < 8; kt++) {
            int c0 = kt * 16 + tig * 2;
            float2 v;
            v = *(const float2*)(r0 + c0);     packhl(v.x, v.y, ahi[kt][0], alo[kt][0]);
            v = *(const float2*)(r1 + c0);     packhl(v.x, v.y, ahi[kt][1], alo[kt][1]);
            v = *(const float2*)(r0 + c0 + 8); packhl(v.x, v.y, ahi[kt][2], alo[kt][2]);
            v = *(const float2*)(r1 + c0 + 8); packhl(v.x, v.y, ahi[kt][3], alo[kt][3]);
        }
    }

    for (int i = tid; i < 8192; i += 512) fb[i] = 0u;    // h=0 in both groups/phases

    if (tid == 0) {
#pragma unroll
        for (int q = 0; q < 4; q++) mbar_init(mb_s + 8 * q, 1);
        asm volatile("fence.mbarrier_init.release.cluster;" ::: "memory");
#pragma unroll
        for (int q = 0; q < 4; q++) mbar_arrive_expect(mb_s + 8 * q, 8192);
    }
    __syncthreads();
    cluster_sync();

    bool s2t = tid < 256;                    // stage-2 threads: b2 = warp, j2 = lane
    int b2 = tid >> 5, j2 = tid & 31;
    float cst[2] = {0.f, 0.f};
    unsigned parr = 0;                       // parity bit per q = g*2+p
    int p = 0;

    for (int s = 0; s < L; s++) {
        int pos = dir ? (L - 1 - s) : s;
#pragma unroll
        for (int g = 0; g < 2; g++) {
            int bg = quad * 16 + g * 8 + b2;
            float p_i = 0.f, p_f = 0.f, p_g = 0.f, p_o = 0.f;
            if (s2t) {                       // early gathers, consumed after HMMA
                int tok = g_tok[bg * LMAX_ + pos];
                const float* pe = g_projE + (dir * 257 + tok) * 1024 + rank * 32 + j2;
                p_i = pe[0]; p_f = pe[256]; p_g = pe[512]; p_o = pe[768];
            }
            int q = g * 2 + p;
            if (s > 0) {
                mbar_wait(mb_s + 8 * q, (parr >> q) & 1);
                parr ^= 1u << q;
                if (tid == 0) mbar_arrive_expect(mb_s + 8 * q, 8192);   // rearm 2 steps ahead
            }

            // ---- HMMA: D[128x8] = Whh_slice . h_g  (3 products, 2 acc chains) ----
            {
                const uint32_t* fbg = fb + q * 2048;
                float a0[4] = {0.f, 0.f, 0.f, 0.f};
                float a1[4] = {0.f, 0.f, 0.f, 0.f};
#pragma unroll
                for (int kt = 0; kt < 8; kt++) {
                    const uint32_t* base = fbg + (kh * 8 + kt) * 128;
                    uint2 bh = *(const uint2*)(base + lane * 2);
                    uint2 bl = *(const uint2*)(base + 64 + lane * 2);
                    mma16816(a0, ahi[kt], bh.x, bh.y);
                    mma16816(a1, ahi[kt], bl.x, bl.y);
                    mma16816(a1, alo[kt], bh.x, bh.y);
                }
                float* sc = scr + (g * 2 + kh) * 1152;
                int m0 = mt * 16 + gid, n0 = tig * 2;
                sc[m0 * 9 + n0]           = a0[0] + a1[0];
                sc[m0 * 9 + n0 + 1]       = a0[1] + a1[1];
                sc[(m0 + 8) * 9 + n0]     = a0[2] + a1[2];
                sc[(m0 + 8) * 9 + n0 + 1] = a0[3] + a1[3];
            }

            if (s2t) {
                // consumers: wait for all 16 warps' scr writes (per-group barrier id!)
                asm volatile("bar.sync %0, 512;" :: "r"(1 + g) : "memory");
                // ---- stage 2: gates + state update + fragment pack ----
                const float* s0 = scr + (g * 2) * 1152;
                const float* s1 = scr + (g * 2 + 1) * 1152;
                float gi = p_i + s0[(      j2) * 9 + b2] + s1[(      j2) * 9 + b2];
                float gf = p_f + s0[( 32 + j2) * 9 + b2] + s1[( 32 + j2) * 9 + b2];
                float gg = p_g + s0[( 64 + j2) * 9 + b2] + s1[( 64 + j2) * 9 + b2];
                float go = p_o + s0[( 96 + j2) * 9 + b2] + s1[( 96 + j2) * 9 + b2];
                float c = sigf(gf) * cst[g] + sigf(gi) * tanhf_(gg);
                cst[g] = c;
                float h = sigf(go) * tanhf_(c);

                g_hout[(((size_t)dir * 64 + bg) * L + pos) * 256 + rank * 32 + j2] = h;

                if (s + 1 < L) {             // pack h -> bf16 hi/lo directly in fragment layout
                    unsigned short hh = bfb(h);
                    unsigned short lh = bfb(h - bff(hh));
                    int ktg_l = j2 >> 4, reg = (j2 >> 3) & 1, tg = (j2 >> 1) & 3, hw = j2 & 1;
                    uint32_t base16 = (uint32_t)(q * 256);
                    uint32_t ehi = ((ktg_l * 2 + 0) * 32 + b2 * 4 + tg) * 2 + reg;
                    uint32_t elo = ((ktg_l * 2 + 1) * 32 + b2 * 4 + tg) * 2 + reg;
                    asm volatile("st.shared.u16 [%0], %1;"
                                 :: "r"(st_s + (base16 + ehi) * 4 + hw * 2), "h"(hh) : "memory");
                    asm volatile("st.shared.u16 [%0], %1;"
                                 :: "r"(st_s + (base16 + elo) * 4 + hw * 2), "h"(lh) : "memory");
                    asm volatile("bar.sync 3, 256;" ::: "memory");   // stage-2 warps only
                    if (tid < 8) {           // 8 x 1KB fragment copies to peers
                        asm volatile("fence.proxy.async.shared::cta;" ::: "memory");
                        uint32_t dst = fb_s + (uint32_t)(((g * 2 + (p ^ 1)) * 2048 + rank * 256) * 4);
                        uint32_t mb  = mb_s + (uint32_t)((g * 2 + (p ^ 1)) * 8);
                        uint32_t src = st_s + (uint32_t)(q * 1024);
                        uint32_t ra, rm;
                        asm volatile("mapa.shared::cluster.u32 %0, %1, %2;" : "=r"(ra) : "r"(dst), "r"(tid));
                        asm volatile("mapa.shared::cluster.u32 %0, %1, %2;" : "=r"(rm) : "r"(mb), "r"(tid));
                        s2s_bulk(ra, src, 1024, rm);
                    }
                }
            } else {
                // producers: post arrival on this group's barrier, run ahead
                asm volatile("bar.arrive %0, 512;" :: "r"(1 + g) : "memory");
            }
        }
        p ^= 1;
    }
    cluster_sync();                          // exit safety
}

// ---------------- K4: final linear on HMMA: (B*L, 512) @ (512, 80) + bias ----------------
#define LIN_SMEM (163840 + 512)
__global__ void __launch_bounds__(256, 1)
k_lin(const float* __restrict__ linb, float* __restrict__ out, int L, int R) {
    extern __shared__ __align__(16) char smc[];
    uint4* sb = (uint4*)smc;                 // [320][32] B-fragments
    float* sbias = (float*)(smc + 163840);
    int tid = threadIdx.x;
    for (int i = tid; i < 10240; i += 256) sb[i] = g_linwF[i];
    if (tid < 80) sbias[tid] = linb[tid];
    __syncthreads();

    int w = tid >> 5, lane = tid & 31, gid = lane >> 2, tig = lane & 3;
    int r0 = blockIdx.x * 128 + w * 16;
    int ra = r0 + gid, rb = r0 + gid + 8;
    bool va = ra < R, vb = rb < R;
    int raz = va ? ra : 0, rbz = vb ? rb : 0;
    int ba = raz / L, pa = raz % L, bb = rbz / L, pb = rbz % L;
    const float* pa0 = g_hout + ((size_t)ba * L + pa) * 256;
    const float* pa1 = g_hout + ((size_t)(64 + ba) * L + pa) * 256;
    const float* pb0 = g_hout + ((size_t)bb * L + pb) * 256;
    const float* pb1 = g_hout + ((size_t)(64 + bb) * L + pb) * 256;

    float acc[10][4];
#pragma unroll
    for (int nt = 0; nt < 10; nt++)
#pragma unroll
        for (int i = 0; i < 4; i++) acc[nt][i] = 0.f;

#pragma unroll 4
    for (int kt = 0; kt < 32; kt++) {
        const float* qa = (kt < 16) ? pa0 : pa1;
        const float* qb = (kt < 16) ? pb0 : pb1;
        int c0 = ((kt * 16) & 255) + tig * 2;
        float2 z = make_float2(0.f, 0.f);
        float2 a00 = va ? *(const float2*)(qa + c0)     : z;
        float2 a10 = vb ? *(const float2*)(qb + c0)     : z;
        float2 a01 = va ? *(const float2*)(qa + c0 + 8) : z;
        float2 a11 = vb ? *(const float2*)(qb + c0 + 8) : z;
        uint32_t ahi[4], alo[4];
        packhl(a00.x, a00.y, ahi[0], alo[0]);
        packhl(a10.x, a10.y, ahi[1], alo[1]);
        packhl(a01.x, a01.y, ahi[2], alo[2]);
        packhl(a11.x, a11.y, ahi[3], alo[3]);
        const uint4* bp = sb + kt * 320 + lane;
#pragma unroll
        for (int nt = 0; nt < 10; nt++) {
            uint4 bf = bp[nt * 32];
            mma16816(acc[nt], ahi, bf.x, bf.y);   // hi*hi
            mma16816(acc[nt], ahi, bf.z, bf.w);   // hi*lo
            mma16816(acc[nt], alo, bf.x, bf.y);   // lo*hi
        }
    }
#pragma unroll
    for (int nt = 0; nt < 10; nt++) {
        int n0 = nt * 8 + tig * 2;
        float b0 = sbias[n0], b1 = sbias[n0 + 1];
        if (va) {
            out[(size_t)ra * MEL_ + n0]     = acc[nt][0] + b0;
            out[(size_t)ra * MEL_ + n0 + 1] = acc[nt][1] + b1;
        }
        if (vb) {
            out[(size_t)rb * MEL_ + n0]     = acc[nt][2] + b0;
            out[(size_t)rb * MEL_ + n0 + 1] = acc[nt][3] + b1;
        }
    }
}

// ---------------- launch ----------------
extern "C" void kernel_launch(void* const* d_in, const int* in_sizes, int n_in,
                              void* d_out, int out_size) {
    const int*   x     = (const int*)  d_in[0];
    const float* embed = (const float*)d_in[1];
    const float* dpw   = (const float*)d_in[2];
    const float* dpb   = (const float*)d_in[3];
    const float* wihf  = (const float*)d_in[4];
    const float* whhf  = (const float*)d_in[5];
    const float* bihf  = (const float*)d_in[6];
    const float* bhhf  = (const float*)d_in[7];
    const float* wihb  = (const float*)d_in[8];
    const float* whhb  = (const float*)d_in[9];
    const float* bihb  = (const float*)d_in[10];
    const float* bhhb  = (const float*)d_in[11];
    const float* linw  = (const float*)d_in[12];
    const float* linb  = (const float*)d_in[13];
    float* out = (float*)d_out;

    int L = out_size / (B_ * MEL_);
    if (L > LMAX_) L = LMAX_;
    int R = B_ * L;

    k_durtab<<<1, 256>>>(embed, dpw, dpb);
    k_expand<<<B_, T_>>>(x);
    k_linprep<<<40, 256>>>(linw);

    int smem_proj = 65 * 128 * 4;              // 33,280 B
    cudaFuncSetAttribute(k_proj, cudaFuncAttributeMaxDynamicSharedMemorySize, smem_proj);
    k_proj<<<dim3(8, 2, 4), 256, smem_proj>>>(embed, wihf, bihf, bhhf, wihb, bihb, bhhb);

    cudaFuncSetAttribute(k_lstm, cudaFuncAttributeMaxDynamicSharedMemorySize, SMEM_LSTM);
    k_lstm<<<64, 512, SMEM_LSTM>>>(whhf, whhb, L);

    cudaFuncSetAttribute(k_lin, cudaFuncAttributeMaxDynamicSharedMemorySize, LIN_SMEM);
    k_lin<<<(R + 127) / 128, 256, LIN_SMEM>>>(linb, out, L, R);
}